// round 1
// baseline (speedup 1.0000x reference)
#include <cuda_runtime.h>
#include <math.h>

#define MAXN 50048
typedef unsigned long long u64;

// ---------------- scratch (static device allocations; no cudaMalloc) ----------------
__device__ float g_h  [MAXN*128];
__device__ float g_x  [MAXN*3];
__device__ float g_hA [MAXN*128];
__device__ float g_hB [MAXN*128];
__device__ float g_agg[MAXN*128];
__device__ float g_tmp[MAXN*128];
__device__ float g_v  [MAXN*128];
__device__ float g_cup[MAXN*3];
__device__ float g_eps[MAXN*3];
__device__ float g_deg[MAXN];

// ---------------- helpers ----------------
__device__ __forceinline__ u64 pk2(float lo, float hi) {
    u64 r; asm("mov.b64 %0,{%1,%2};" : "=l"(r) : "f"(lo), "f"(hi)); return r;
}
__device__ __forceinline__ void fma2(u64& d, u64 a, u64 b) {
    asm("fma.rn.f32x2 %0,%1,%2,%0;" : "+l"(d) : "l"(a), "l"(b));
}
__device__ __forceinline__ float2 up2(u64 v) {
    float2 f; asm("mov.b64 {%0,%1},%2;" : "=f"(f.x), "=f"(f.y) : "l"(v)); return f;
}
__device__ __forceinline__ float silu(float x) {
    return __fdividef(x, 1.0f + __expf(-x));
}
__device__ __forceinline__ void red4(float* p, float a, float b, float c, float d) {
    asm volatile("red.global.add.v4.f32 [%0],{%1,%2,%3,%4};" :: "l"(p), "f"(a), "f"(b), "f"(c), "f"(d) : "memory");
}
__device__ __forceinline__ void red1(float* p, float a) {
    asm volatile("red.global.add.f32 [%0],%1;" :: "l"(p), "f"(a) : "memory");
}

// 128x128x(K) register-blocked GEMM core. sAT is [k][m] (transposed), sB is [k][j].
// Thread (ty,tx) produces C[ty*8..+7][tx*8..+7] as 8x4 f32x2 accumulators.
__device__ __forceinline__ void tile_gemm(const float* __restrict__ sAT,
                                          const float* __restrict__ sB,
                                          int er, int jc, int K, u64 acc[8][4]) {
#pragma unroll
    for (int r = 0; r < 8; r++)
#pragma unroll
        for (int c = 0; c < 4; c++) acc[r][c] = 0ull;
#pragma unroll 2
    for (int k = 0; k < K; k++) {
        const float4 a0 = *(const float4*)(sAT + k*128 + er);
        const float4 a1 = *(const float4*)(sAT + k*128 + er + 4);
        const float4 b0 = *(const float4*)(sB  + k*128 + jc);
        const float4 b1 = *(const float4*)(sB  + k*128 + jc + 4);
        u64 bb0 = pk2(b0.x, b0.y), bb1 = pk2(b0.z, b0.w);
        u64 bb2 = pk2(b1.x, b1.y), bb3 = pk2(b1.z, b1.w);
        float av[8] = {a0.x, a0.y, a0.z, a0.w, a1.x, a1.y, a1.z, a1.w};
#pragma unroll
        for (int r = 0; r < 8; r++) {
            u64 ar = pk2(av[r], av[r]);
            fma2(acc[r][0], ar, bb0);
            fma2(acc[r][1], ar, bb1);
            fma2(acc[r][2], ar, bb2);
            fma2(acc[r][3], ar, bb3);
        }
    }
}

// ---------------- small utility kernels ----------------
__global__ void zero_kernel(float* p, int n) {
    int i = blockIdx.x * blockDim.x + threadIdx.x;
    if (i < n) p[i] = 0.0f;
}
__global__ void copy_kernel(const float* __restrict__ s, float* d, int n) {
    int i = blockIdx.x * blockDim.x + threadIdx.x;
    if (i < n) d[i] = s[i];
}
__global__ void indeg_kernel(const int* __restrict__ col, int E, float* deg) {
    int i = blockIdx.x * blockDim.x + threadIdx.x;
    if (i < E) atomicAdd(&deg[col[i]], 1.0f);
}

// ---------------- node-level tiled GEMM: out[n][128] = act(beta*out + A[n][0..K)@W + bias) ----------------
__global__ __launch_bounds__(256) void gemm_node(
    const float* __restrict__ A, int K,
    const float* __restrict__ W,
    const float* __restrict__ bias,
    float* __restrict__ out, int n, int beta, int act)
{
    extern __shared__ float sm[];
    float* sAT = sm;            // [k][m]
    float* sB  = sm + 16384;    // [k][j]
    int tid = threadIdx.x;
    int m0 = blockIdx.x * 128;

    if (K == 128) {
        for (int idx = tid; idx < 128*128; idx += 256) {
            int m = idx >> 7, k = idx & 127;
            int gm = m0 + m; if (gm >= n) gm = n - 1;
            sAT[k*128 + m] = A[gm*128 + k];
        }
    } else {
        for (int idx = tid; idx < K*128; idx += 256) {
            int m = idx / K, k = idx - m*K;
            int gm = m0 + m; if (gm >= n) gm = n - 1;
            sAT[k*128 + m] = A[gm*K + k];
        }
    }
    for (int idx = tid; idx < K*128; idx += 256) sB[idx] = W[idx];
    __syncthreads();

    int ty = tid >> 4, tx = tid & 15;
    int er = ty * 8, jc = tx * 8;
    u64 acc[8][4];
    tile_gemm(sAT, sB, er, jc, K, acc);

    float bv[8];
#pragma unroll
    for (int c = 0; c < 8; c++) bv[c] = bias ? bias[jc + c] : 0.0f;

#pragma unroll
    for (int r = 0; r < 8; r++) {
        int gm = m0 + er + r;
        if (gm >= n) continue;
        float* o = out + (size_t)gm * 128 + jc;
#pragma unroll
        for (int c2 = 0; c2 < 4; c2++) {
            float2 p = up2(acc[r][c2]);
            float v0 = p.x + bv[2*c2], v1 = p.y + bv[2*c2 + 1];
            if (beta) { v0 += o[2*c2]; v1 += o[2*c2 + 1]; }
            if (act == 1) { v0 = silu(v0); v1 = silu(v1); }
            o[2*c2] = v0; o[2*c2 + 1] = v1;
        }
    }
}

// ---------------- fused edge kernel (message-passing layer) ----------------
// per 128-edge tile: t1 gather -> silu -> GEMM(m_w2)+silu = msg -> scatter agg,
// then GEMM(c_w1)+silu -> dot(c_w2) -> tanh -> scatter cupd
__global__ __launch_bounds__(256) void edge_layer(
    const int* __restrict__ eRow, const int* __restrict__ eCol, int E,
    const float* __restrict__ x,
    const float* __restrict__ hA, const float* __restrict__ hB,
    const float* __restrict__ w1c, const float* __restrict__ b1,
    const float* __restrict__ W2, const float* __restrict__ b2,
    const float* __restrict__ Cw1, const float* __restrict__ cb1,
    const float* __restrict__ cw2,
    float* __restrict__ agg, float* __restrict__ cupd)
{
    extern __shared__ float sm[];
    float* sAT = sm;
    float* sB  = sm + 16384;
    int*   sRow   = (int*)(sm + 32768);
    int*   sCol   = sRow + 128;
    int*   sValid = sCol + 128;
    float* sDist  = (float*)(sValid + 128);
    float* sRelx  = sDist + 128;
    float* sRely  = sRelx + 128;
    float* sRelz  = sRely + 128;

    int tid = threadIdx.x;
    int e0 = blockIdx.x * 128;

    if (tid < 128) {
        int e = e0 + tid;
        int valid = (e < E); if (!valid) e = E - 1;
        int r = eRow[e], c = eCol[e];
        float rx = x[r*3]   - x[c*3];
        float ry = x[r*3+1] - x[c*3+1];
        float rz = x[r*3+2] - x[c*3+2];
        float d = sqrtf(rx*rx + ry*ry + rz*rz);
        sRow[tid] = r; sCol[tid] = c; sValid[tid] = valid;
        sDist[tid] = d; sRelx[tid] = rx; sRely[tid] = ry; sRelz[tid] = rz;
    }
    {   // load W2 into sB (coalesced float4)
        const float4* src = (const float4*)W2;
        float4* dst = (float4*)sB;
        for (int i = tid; i < 4096; i += 256) dst[i] = src[i];
    }
    __syncthreads();

    {   // build u = silu(t1) into sAT[k][e]
        int e = tid >> 1;
        int j0 = (tid & 1) * 64;
        int r = sRow[e], c = sCol[e];
        float d = sDist[e];
        const float4* pa  = (const float4*)(hA  + (size_t)r*128 + j0);
        const float4* pb  = (const float4*)(hB  + (size_t)c*128 + j0);
        const float4* pw  = (const float4*)(w1c + j0);
        const float4* pb1 = (const float4*)(b1  + j0);
#pragma unroll
        for (int q = 0; q < 16; q++) {
            float4 a = pa[q], b = pb[q], w = pw[q], bb = pb1[q];
            int j = j0 + q*4;
            sAT[(j  )*128 + e] = silu(a.x + b.x + d*w.x + bb.x);
            sAT[(j+1)*128 + e] = silu(a.y + b.y + d*w.y + bb.y);
            sAT[(j+2)*128 + e] = silu(a.z + b.z + d*w.z + bb.z);
            sAT[(j+3)*128 + e] = silu(a.w + b.w + d*w.w + bb.w);
        }
    }
    __syncthreads();

    int ty = tid >> 4, tx = tid & 15;
    int er = ty * 8, jc = tx * 8;
    u64 acc[8][4];
    tile_gemm(sAT, sB, er, jc, 128, acc);
    __syncthreads();   // all reads of sAT/sB done

    // msg = silu(t2 + b2); scatter into agg; stash msg into sAT (transposed) for GEMM2
    {
        float bv[8];
#pragma unroll
        for (int c = 0; c < 8; c++) bv[c] = b2[jc + c];
#pragma unroll
        for (int r = 0; r < 8; r++) {
            int e = er + r;
            float msg[8];
#pragma unroll
            for (int c2 = 0; c2 < 4; c2++) {
                float2 p = up2(acc[r][c2]);
                msg[2*c2]   = silu(p.x + bv[2*c2]);
                msg[2*c2+1] = silu(p.y + bv[2*c2+1]);
            }
#pragma unroll
            for (int c = 0; c < 8; c++) sAT[(jc + c)*128 + e] = msg[c];
            if (sValid[e]) {
                float* p = agg + (size_t)sCol[e]*128 + jc;
                red4(p,     msg[0], msg[1], msg[2], msg[3]);
                red4(p + 4, msg[4], msg[5], msg[6], msg[7]);
            }
        }
    }
    {   // load c_w1 into sB
        const float4* src = (const float4*)Cw1;
        float4* dst = (float4*)sB;
        for (int i = tid; i < 4096; i += 256) dst[i] = src[i];
    }
    __syncthreads();

    tile_gemm(sAT, sB, er, jc, 128, acc);

    // w = silu(.. + cb1); partial dot with c_w2; shuffle-reduce over tx; tanh; scatter cupd
    float cwv[8], cbv[8];
#pragma unroll
    for (int c = 0; c < 8; c++) { cwv[c] = cw2[jc + c]; cbv[c] = cb1[jc + c]; }
    float part[8];
#pragma unroll
    for (int r = 0; r < 8; r++) {
        float p = 0.0f;
#pragma unroll
        for (int c2 = 0; c2 < 4; c2++) {
            float2 t = up2(acc[r][c2]);
            p += silu(t.x + cbv[2*c2]) * cwv[2*c2];
            p += silu(t.y + cbv[2*c2+1]) * cwv[2*c2+1];
        }
        part[r] = p;
    }
#pragma unroll
    for (int m = 8; m >= 1; m >>= 1)
#pragma unroll
        for (int r = 0; r < 8; r++)
            part[r] += __shfl_xor_sync(0xffffffffu, part[r], m);

    if (tx == 0) {
#pragma unroll
        for (int r = 0; r < 8; r++) {
            int e = er + r;
            if (!sValid[e]) continue;
            float cm = tanhf(part[r]);
            float f = __fdividef(cm, sDist[e] + 1e-8f);
            int c = sCol[e];
            red1(cupd + c*3 + 0, f * sRelx[e]);
            red1(cupd + c*3 + 1, f * sRely[e]);
            red1(cupd + c*3 + 2, f * sRelz[e]);
        }
    }
}

// ---------------- fused edge kernel (epsilon head) ----------------
__global__ __launch_bounds__(256) void edge_eps(
    const int* __restrict__ eRow, const int* __restrict__ eCol, int E,
    const float* __restrict__ x,
    const float* __restrict__ hA, const float* __restrict__ hB,
    const float* __restrict__ wRel,   // em_w1 rows 256..259 (relx,rely,relz,dist)
    const float* __restrict__ b1,
    const float* __restrict__ W2, const float* __restrict__ b2,
    const float* __restrict__ Cw1, const float* __restrict__ cb1,
    const float* __restrict__ cw2,   // ec_w2 [128][3]
    const float* __restrict__ cb2,   // ec_b2 [3]
    float* __restrict__ eps)
{
    extern __shared__ float sm[];
    float* sAT = sm;
    float* sB  = sm + 16384;
    int*   sRow   = (int*)(sm + 32768);
    int*   sCol   = sRow + 128;
    int*   sValid = sCol + 128;
    float* sDist  = (float*)(sValid + 128);
    float* sRelx  = sDist + 128;
    float* sRely  = sRelx + 128;
    float* sRelz  = sRely + 128;

    int tid = threadIdx.x;
    int e0 = blockIdx.x * 128;

    if (tid < 128) {
        int e = e0 + tid;
        int valid = (e < E); if (!valid) e = E - 1;
        int r = eRow[e], c = eCol[e];
        float rx = x[r*3]   - x[c*3];
        float ry = x[r*3+1] - x[c*3+1];
        float rz = x[r*3+2] - x[c*3+2];
        float d = sqrtf(rx*rx + ry*ry + rz*rz);
        sRow[tid] = r; sCol[tid] = c; sValid[tid] = valid;
        sDist[tid] = d; sRelx[tid] = rx; sRely[tid] = ry; sRelz[tid] = rz;
    }
    {
        const float4* src = (const float4*)W2;
        float4* dst = (float4*)sB;
        for (int i = tid; i < 4096; i += 256) dst[i] = src[i];
    }
    __syncthreads();

    {
        int e = tid >> 1;
        int j0 = (tid & 1) * 64;
        int r = sRow[e], c = sCol[e];
        float d = sDist[e], rx = sRelx[e], ry = sRely[e], rz = sRelz[e];
        const float4* pa  = (const float4*)(hA + (size_t)r*128 + j0);
        const float4* pb  = (const float4*)(hB + (size_t)c*128 + j0);
        const float4* pwx = (const float4*)(wRel + j0);
        const float4* pwy = (const float4*)(wRel + 128 + j0);
        const float4* pwz = (const float4*)(wRel + 256 + j0);
        const float4* pwd = (const float4*)(wRel + 384 + j0);
        const float4* pb1 = (const float4*)(b1 + j0);
#pragma unroll
        for (int q = 0; q < 16; q++) {
            float4 a = pa[q], b = pb[q];
            float4 wx = pwx[q], wy = pwy[q], wz = pwz[q], wd = pwd[q], bb = pb1[q];
            int j = j0 + q*4;
            sAT[(j  )*128 + e] = silu(a.x + b.x + rx*wx.x + ry*wy.x + rz*wz.x + d*wd.x + bb.x);
            sAT[(j+1)*128 + e] = silu(a.y + b.y + rx*wx.y + ry*wy.y + rz*wz.y + d*wd.y + bb.y);
            sAT[(j+2)*128 + e] = silu(a.z + b.z + rx*wx.z + ry*wy.z + rz*wz.z + d*wd.z + bb.z);
            sAT[(j+3)*128 + e] = silu(a.w + b.w + rx*wx.w + ry*wy.w + rz*wz.w + d*wd.w + bb.w);
        }
    }
    __syncthreads();

    int ty = tid >> 4, tx = tid & 15;
    int er = ty * 8, jc = tx * 8;
    u64 acc[8][4];
    tile_gemm(sAT, sB, er, jc, 128, acc);
    __syncthreads();

    {   // em = silu(+b2) -> sAT
        float bv[8];
#pragma unroll
        for (int c = 0; c < 8; c++) bv[c] = b2[jc + c];
#pragma unroll
        for (int r = 0; r < 8; r++) {
            int e = er + r;
#pragma unroll
            for (int c2 = 0; c2 < 4; c2++) {
                float2 p = up2(acc[r][c2]);
                sAT[(jc + 2*c2    )*128 + e] = silu(p.x + bv[2*c2]);
                sAT[(jc + 2*c2 + 1)*128 + e] = silu(p.y + bv[2*c2+1]);
            }
        }
    }
    {
        const float4* src = (const float4*)Cw1;
        float4* dst = (float4*)sB;
        for (int i = tid; i < 4096; i += 256) dst[i] = src[i];
    }
    __syncthreads();

    tile_gemm(sAT, sB, er, jc, 128, acc);

    // w = silu(+cb1); 3-way dot with ec_w2; reduce; scatter eps
    float cbv[8];
#pragma unroll
    for (int c = 0; c < 8; c++) cbv[c] = cb1[jc + c];
    float cwv[8][3];
#pragma unroll
    for (int c = 0; c < 8; c++) {
        cwv[c][0] = cw2[(jc + c)*3 + 0];
        cwv[c][1] = cw2[(jc + c)*3 + 1];
        cwv[c][2] = cw2[(jc + c)*3 + 2];
    }
    float part[8][3];
#pragma unroll
    for (int r = 0; r < 8; r++) {
        float p0 = 0, p1 = 0, p2 = 0;
#pragma unroll
        for (int c2 = 0; c2 < 4; c2++) {
            float2 t = up2(acc[r][c2]);
            float w0 = silu(t.x + cbv[2*c2]);
            float w1 = silu(t.y + cbv[2*c2+1]);
            p0 += w0*cwv[2*c2][0] + w1*cwv[2*c2+1][0];
            p1 += w0*cwv[2*c2][1] + w1*cwv[2*c2+1][1];
            p2 += w0*cwv[2*c2][2] + w1*cwv[2*c2+1][2];
        }
        part[r][0] = p0; part[r][1] = p1; part[r][2] = p2;
    }
#pragma unroll
    for (int m = 8; m >= 1; m >>= 1)
#pragma unroll
        for (int r = 0; r < 8; r++) {
            part[r][0] += __shfl_xor_sync(0xffffffffu, part[r][0], m);
            part[r][1] += __shfl_xor_sync(0xffffffffu, part[r][1], m);
            part[r][2] += __shfl_xor_sync(0xffffffffu, part[r][2], m);
        }

    if (tx == 0) {
#pragma unroll
        for (int r = 0; r < 8; r++) {
            int e = er + r;
            if (!sValid[e]) continue;
            int c = sCol[e];
            red1(eps + c*3 + 0, part[r][0] + cb2[0]);
            red1(eps + c*3 + 1, part[r][1] + cb2[1]);
            red1(eps + c*3 + 2, part[r][2] + cb2[2]);
        }
    }
}

// ---------------- residual + LayerNorm + x update ----------------
__global__ __launch_bounds__(128) void ln_update(
    const float* __restrict__ v, const float* __restrict__ g, const float* __restrict__ b,
    float* __restrict__ h, float* __restrict__ x,
    const float* __restrict__ cupd, const float* __restrict__ deg)
{
    int node = blockIdx.x;
    int j = threadIdx.x;
    float val = h[(size_t)node*128 + j] + v[(size_t)node*128 + j];
    float s = val, s2 = val * val;
#pragma unroll
    for (int m = 16; m >= 1; m >>= 1) {
        s  += __shfl_xor_sync(0xffffffffu, s, m);
        s2 += __shfl_xor_sync(0xffffffffu, s2, m);
    }
    __shared__ float ws[4], ws2[4];
    int wid = j >> 5, lane = j & 31;
    if (lane == 0) { ws[wid] = s; ws2[wid] = s2; }
    __syncthreads();
    s  = ws[0] + ws[1] + ws[2] + ws[3];
    s2 = ws2[0] + ws2[1] + ws2[2] + ws2[3];
    float mu = s * (1.0f / 128.0f);
    float var = s2 * (1.0f / 128.0f) - mu * mu;
    float out = (val - mu) * rsqrtf(var + 1e-5f) * g[j] + b[j];
    h[(size_t)node*128 + j] = out;
    if (j < 3) x[node*3 + j] += cupd[node*3 + j] / (deg[node] + 1.0f);
}

// ---------------- eps node head ----------------
__global__ void eps_final(const float* __restrict__ t, const float* __restrict__ W,
                          const float* __restrict__ b2, float* __restrict__ eps)
{
    int node = blockIdx.x;
    int tid = threadIdx.x;   // 96 threads
    int d = tid >> 5, lane = tid & 31;
    float p = 0.0f;
    for (int k = lane; k < 128; k += 32) p += t[(size_t)node*128 + k] * W[k*3 + d];
#pragma unroll
    for (int m = 16; m >= 1; m >>= 1) p += __shfl_xor_sync(0xffffffffu, p, m);
    if (lane == 0) eps[node*3 + d] += p + b2[d];
}

// ---------------- pack output: [h | x | eps] ----------------
__global__ void pack_kernel(const float* __restrict__ h, const float* __restrict__ x,
                            const float* __restrict__ eps, float* __restrict__ out, int n)
{
    int i = blockIdx.x * blockDim.x + threadIdx.x;
    int nh = n * 128;
    if (i < nh) out[i] = h[i];
    else if (i < nh + 3*n) out[i] = x[i - nh];
    else if (i < nh + 6*n) out[i] = eps[i - nh - 3*n];
}

// ---------------- host ----------------
static const int GEMM_SMEM = 131072;
static const int EDGE_SMEM = 131072 + 7*128*4;

extern "C" void kernel_launch(void* const* d_in, const int* in_sizes, int n_in,
                              void* d_out, int out_size)
{
    const float* in_h  = (const float*)d_in[0];
    const float* in_x  = (const float*)d_in[1];
    const int*   eidx  = (const int*)d_in[2];
    const float* emb_w = (const float*)d_in[3];
    const float* emb_b = (const float*)d_in[4];
    const float* m_w1  = (const float*)d_in[5];
    const float* m_b1  = (const float*)d_in[6];
    const float* m_w2  = (const float*)d_in[7];
    const float* m_b2  = (const float*)d_in[8];
    const float* c_w1  = (const float*)d_in[9];
    const float* c_b1  = (const float*)d_in[10];
    const float* c_w2  = (const float*)d_in[11];
    const float* n_w1  = (const float*)d_in[12];
    const float* n_b1  = (const float*)d_in[13];
    const float* n_w2  = (const float*)d_in[14];
    const float* n_b2  = (const float*)d_in[15];
    const float* ln_g  = (const float*)d_in[16];
    const float* ln_b  = (const float*)d_in[17];
    const float* em_w1 = (const float*)d_in[18];
    const float* em_b1 = (const float*)d_in[19];
    const float* em_w2 = (const float*)d_in[20];
    const float* em_b2 = (const float*)d_in[21];
    const float* ec_w1 = (const float*)d_in[22];
    const float* ec_b1 = (const float*)d_in[23];
    const float* ec_w2 = (const float*)d_in[24];
    const float* ec_b2 = (const float*)d_in[25];
    const float* eh_w1 = (const float*)d_in[26];
    const float* eh_b1 = (const float*)d_in[27];
    const float* eh_w2 = (const float*)d_in[28];
    const float* eh_b2 = (const float*)d_in[29];

    int n = in_sizes[0] / 64;
    int E = in_sizes[2] / 2;
    const int* eRow = eidx;
    const int* eCol = eidx + E;

    float *h, *x, *hA, *hB, *agg, *tmp, *v, *cup, *eps, *deg;
    cudaGetSymbolAddress((void**)&h,   g_h);
    cudaGetSymbolAddress((void**)&x,   g_x);
    cudaGetSymbolAddress((void**)&hA,  g_hA);
    cudaGetSymbolAddress((void**)&hB,  g_hB);
    cudaGetSymbolAddress((void**)&agg, g_agg);
    cudaGetSymbolAddress((void**)&tmp, g_tmp);
    cudaGetSymbolAddress((void**)&v,   g_v);
    cudaGetSymbolAddress((void**)&cup, g_cup);
    cudaGetSymbolAddress((void**)&eps, g_eps);
    cudaGetSymbolAddress((void**)&deg, g_deg);

    cudaFuncSetAttribute(gemm_node,  cudaFuncAttributeMaxDynamicSharedMemorySize, GEMM_SMEM);
    cudaFuncSetAttribute(edge_layer, cudaFuncAttributeMaxDynamicSharedMemorySize, EDGE_SMEM);
    cudaFuncSetAttribute(edge_eps,   cudaFuncAttributeMaxDynamicSharedMemorySize, EDGE_SMEM);

    int gN = (n + 127) / 128;
    int gE = (E + 127) / 128;

    // in-degree
    zero_kernel<<<(n + 255)/256, 256>>>(deg, n);
    indeg_kernel<<<(E + 255)/256, 256>>>(eCol, E, deg);

    // embedding + x copy
    gemm_node<<<gN, 256, GEMM_SMEM>>>(in_h, 64, emb_w, emb_b, h, n, 0, 0);
    copy_kernel<<<(3*n + 255)/256, 256>>>(in_x, x, 3*n);

    for (int i = 0; i < 4; i++) {
        const float* w1 = m_w1 + (size_t)i*257*128;
        gemm_node<<<gN, 256, GEMM_SMEM>>>(h, 128, w1,          nullptr, hA, n, 0, 0);
        gemm_node<<<gN, 256, GEMM_SMEM>>>(h, 128, w1 + 128*128, nullptr, hB, n, 0, 0);
        zero_kernel<<<(n*128 + 255)/256, 256>>>(agg, n*128);
        zero_kernel<<<(3*n + 255)/256, 256>>>(cup, 3*n);
        edge_layer<<<gE, 256, EDGE_SMEM>>>(
            eRow, eCol, E, x, hA, hB,
            w1 + 256*128, m_b1 + i*128,
            m_w2 + (size_t)i*128*128, m_b2 + i*128,
            c_w1 + (size_t)i*128*128, c_b1 + i*128, c_w2 + i*128,
            agg, cup);
        gemm_node<<<gN, 256, GEMM_SMEM>>>(h,   128, n_w1 + (size_t)i*256*128,           nullptr,      tmp, n, 0, 0);
        gemm_node<<<gN, 256, GEMM_SMEM>>>(agg, 128, n_w1 + (size_t)i*256*128 + 128*128, n_b1 + i*128, tmp, n, 1, 1);
        gemm_node<<<gN, 256, GEMM_SMEM>>>(tmp, 128, n_w2 + (size_t)i*128*128,           n_b2 + i*128, v,   n, 0, 0);
        ln_update<<<n, 128>>>(v, ln_g + i*128, ln_b + i*128, h, x, cup, deg);
    }

    // epsilon head
    gemm_node<<<gN, 256, GEMM_SMEM>>>(h, 128, em_w1,            nullptr, hA, n, 0, 0);
    gemm_node<<<gN, 256, GEMM_SMEM>>>(h, 128, em_w1 + 128*128,  nullptr, hB, n, 0, 0);
    zero_kernel<<<(3*n + 255)/256, 256>>>(eps, 3*n);
    edge_eps<<<gE, 256, EDGE_SMEM>>>(
        eRow, eCol, E, x, hA, hB,
        em_w1 + 256*128, em_b1,
        em_w2, em_b2, ec_w1, ec_b1, ec_w2, ec_b2, eps);
    gemm_node<<<gN, 256, GEMM_SMEM>>>(h, 128, eh_w1,            nullptr, tmp, n, 0, 0);
    gemm_node<<<gN, 256, GEMM_SMEM>>>(x, 3,   eh_w1 + 128*128,  eh_b1,   tmp, n, 1, 1);
    eps_final<<<n, 96>>>(tmp, eh_w2, eh_b2, eps);

    pack_kernel<<<(n*134 + 255)/256, 256>>>(h, x, eps, (float*)d_out, n);
}

// round 4
// speedup vs baseline: 1.6478x; 1.6478x over previous
#include <cuda_runtime.h>
#include <math.h>
#include <stdint.h>

#define MAXN 50048
typedef unsigned long long u64;

// ---------------- scratch (static device arrays; no cudaMalloc) ----------------
__device__ float g_h  [MAXN*128];
__device__ float g_x  [MAXN*3];
__device__ float g_hA [MAXN*128];
__device__ float g_hB [MAXN*128];
__device__ float g_agg[MAXN*128];
__device__ float g_tmp[MAXN*128];
__device__ float g_v  [MAXN*128];
__device__ float g_cup[MAXN*3];
__device__ float g_eps[MAXN*3];
__device__ float g_deg[MAXN];

// ---------------- helpers ----------------
__device__ __forceinline__ float silu(float v) { return __fdividef(v, 1.0f + __expf(-v)); }
__device__ __forceinline__ uint32_t f2tf(float f) {
    uint32_t r; asm("cvt.rna.tf32.f32 %0, %1;" : "=r"(r) : "f"(f)); return r;
}
__device__ __forceinline__ void mma8(float d[4], uint32_t a0, uint32_t a1, uint32_t a2, uint32_t a3,
                                     uint32_t b0, uint32_t b1) {
    asm volatile(
        "mma.sync.aligned.m16n8k8.row.col.f32.tf32.tf32.f32 "
        "{%0,%1,%2,%3},{%4,%5,%6,%7},{%8,%9},{%0,%1,%2,%3};"
        : "+f"(d[0]), "+f"(d[1]), "+f"(d[2]), "+f"(d[3])
        : "r"(a0), "r"(a1), "r"(a2), "r"(a3), "r"(b0), "r"(b1));
}
__device__ __forceinline__ void red2(float* p, float a, float b) {
    asm volatile("red.global.add.v2.f32 [%0],{%1,%2};" :: "l"(p), "f"(a), "f"(b) : "memory");
}
__device__ __forceinline__ void red1(float* p, float a) {
    asm volatile("red.global.add.f32 [%0],%1;" :: "l"(p), "f"(a) : "memory");
}

#define STRIDE 136
#define SA_BYTES (128*STRIDE*4)   // 69632
#define SB_OFF   SA_BYTES
#define SMEM_AB  (2*SA_BYTES)     // 139264

// warp-tile MMA: C(warp 32x64 of 128x128) = A[128xK] @ B[Kx128]
// sA: [m][k] tf32 stride STRIDE; sB: [k][n] tf32 stride STRIDE
__device__ __forceinline__ void mma_tile(const uint32_t* __restrict__ sA,
                                         const uint32_t* __restrict__ sB,
                                         int warpM, int warpN, int lane, int K,
                                         float acc[2][8][4]) {
#pragma unroll
    for (int mi = 0; mi < 2; mi++)
#pragma unroll
        for (int ni = 0; ni < 8; ni++)
#pragma unroll
            for (int j = 0; j < 4; j++) acc[mi][ni][j] = 0.0f;
    int l4 = lane >> 2, lq = lane & 3;
    int rb = warpM * 32 + l4;
    int nb = warpN * 64 + l4;
    for (int k0 = 0; k0 < K; k0 += 8) {
        uint32_t a[2][4];
#pragma unroll
        for (int mi = 0; mi < 2; mi++) {
            int r = rb + mi * 16;
            a[mi][0] = sA[(r    ) * STRIDE + k0 + lq];
            a[mi][1] = sA[(r + 8) * STRIDE + k0 + lq];
            a[mi][2] = sA[(r    ) * STRIDE + k0 + lq + 4];
            a[mi][3] = sA[(r + 8) * STRIDE + k0 + lq + 4];
        }
#pragma unroll
        for (int ni = 0; ni < 8; ni++) {
            int n = nb + ni * 8;
            uint32_t b0 = sB[(k0 + lq    ) * STRIDE + n];
            uint32_t b1 = sB[(k0 + lq + 4) * STRIDE + n];
            mma8(acc[0][ni], a[0][0], a[0][1], a[0][2], a[0][3], b0, b1);
            mma8(acc[1][ni], a[1][0], a[1][1], a[1][2], a[1][3], b0, b1);
        }
    }
}

// ---------------- small utility kernels ----------------
__global__ void zero_kernel(float* p, int n) {
    int i = blockIdx.x * blockDim.x + threadIdx.x;
    if (i < n) p[i] = 0.0f;
}
__global__ void copy_kernel(const float* __restrict__ s, float* d, int n) {
    int i = blockIdx.x * blockDim.x + threadIdx.x;
    if (i < n) d[i] = s[i];
}
__global__ void indeg_kernel(const int* __restrict__ col, int E, float* deg) {
    int i = blockIdx.x * blockDim.x + threadIdx.x;
    if (i < E) atomicAdd(&deg[col[i]], 1.0f);
}

// ---------------- node GEMM (tf32 mma): out = act(beta*out + A@W + bias) ----------------
__global__ __launch_bounds__(256) void gemm_mma(
    const float* __restrict__ A, int K,
    const float* __restrict__ W,
    const float* __restrict__ bias,
    float* __restrict__ out, int n, int beta, int act)
{
    extern __shared__ char smem[];
    uint32_t* sA = (uint32_t*)smem;
    uint32_t* sB = (uint32_t*)(smem + SB_OFF);
    int tid = threadIdx.x, wid = tid >> 5, lane = tid & 31;
    int warpM = wid & 3, warpN = wid >> 2;
    int m0 = blockIdx.x * 128;

    if (K == 128) {
        for (int idx = tid; idx < 16384; idx += 256) {
            int m = idx >> 7, k = idx & 127;
            int gm = m0 + m; if (gm >= n) gm = n - 1;
            sA[m * STRIDE + k] = f2tf(A[(size_t)gm * 128 + k]);
        }
    } else {  // K == 64
        for (int idx = tid; idx < 8192; idx += 256) {
            int m = idx >> 6, k = idx & 63;
            int gm = m0 + m; if (gm >= n) gm = n - 1;
            sA[m * STRIDE + k] = f2tf(A[(size_t)gm * 64 + k]);
        }
    }
    for (int idx = tid; idx < K * 128; idx += 256) {
        int k = idx >> 7, nn = idx & 127;
        sB[k * STRIDE + nn] = f2tf(W[k * 128 + nn]);
    }
    __syncthreads();

    float acc[2][8][4];
    mma_tile(sA, sB, warpM, warpN, lane, K, acc);

    int l4 = lane >> 2, q2 = (lane & 3) * 2;
#pragma unroll
    for (int mi = 0; mi < 2; mi++)
#pragma unroll
        for (int half = 0; half < 2; half++) {
            int gm = m0 + warpM * 32 + mi * 16 + l4 + half * 8;
            if (gm >= n) continue;
            float* orow = out + (size_t)gm * 128;
#pragma unroll
            for (int ni = 0; ni < 8; ni++) {
                int c = warpN * 64 + ni * 8 + q2;
                float v0 = acc[mi][ni][half * 2 + 0];
                float v1 = acc[mi][ni][half * 2 + 1];
                if (bias) { v0 += __ldg(bias + c); v1 += __ldg(bias + c + 1); }
                if (beta) { float2 o = *(float2*)(orow + c); v0 += o.x; v1 += o.y; }
                if (act)  { v0 = silu(v0); v1 = silu(v1); }
                *(float2*)(orow + c) = make_float2(v0, v1);
            }
        }
}

// ---------------- fused edge kernel (message-passing layer) ----------------
__global__ __launch_bounds__(256) void edge_layer_mma(
    const int* __restrict__ eRow, const int* __restrict__ eCol, int E,
    const float* __restrict__ x,
    const float* __restrict__ hA, const float* __restrict__ hB,
    const float* __restrict__ w1c, const float* __restrict__ b1,
    const float* __restrict__ W2, const float* __restrict__ b2,
    const float* __restrict__ Cw1, const float* __restrict__ cb1,
    const float* __restrict__ cw2,
    float* __restrict__ agg, float* __restrict__ cupd)
{
    extern __shared__ char smem[];
    uint32_t* sA = (uint32_t*)smem;
    uint32_t* sB = (uint32_t*)(smem + SB_OFF);
    char* aux = smem + SMEM_AB;
    int*   sRow   = (int*)(aux);
    int*   sCol   = (int*)(aux + 512);
    int*   sValid = (int*)(aux + 1024);
    float* sDist  = (float*)(aux + 1536);
    float* sRelx  = (float*)(aux + 2048);
    float* sRely  = (float*)(aux + 2560);
    float* sRelz  = (float*)(aux + 3072);
    float* sPart  = (float*)(aux + 3584);

    int tid = threadIdx.x, wid = tid >> 5, lane = tid & 31;
    int warpM = wid & 3, warpN = wid >> 2;
    int e0 = blockIdx.x * 128;

    if (tid < 128) {
        sPart[tid] = 0.0f;
        int e = e0 + tid;
        int valid = (e < E); if (!valid) e = E - 1;
        int r = eRow[e], c = eCol[e];
        float rx = x[r*3]   - x[c*3];
        float ry = x[r*3+1] - x[c*3+1];
        float rz = x[r*3+2] - x[c*3+2];
        float d = sqrtf(rx*rx + ry*ry + rz*rz);
        sRow[tid] = r; sCol[tid] = c; sValid[tid] = valid;
        sDist[tid] = d; sRelx[tid] = rx; sRely[tid] = ry; sRelz[tid] = rz;
    }
    for (int idx = tid; idx < 16384; idx += 256) {   // sB = m_w2 [k][n]
        int k = idx >> 7, nn = idx & 127;
        sB[k * STRIDE + nn] = f2tf(W2[k * 128 + nn]);
    }
    __syncthreads();

    {   // sA[e][k] = silu(t1), two threads per edge
        int e = tid >> 1, j0 = (tid & 1) * 64;
        int r = sRow[e], c = sCol[e];
        float d = sDist[e];
        const float4* pa  = (const float4*)(hA  + (size_t)r * 128 + j0);
        const float4* pb  = (const float4*)(hB  + (size_t)c * 128 + j0);
        const float4* pw  = (const float4*)(w1c + j0);
        const float4* pb1 = (const float4*)(b1  + j0);
        uint32_t* dst = sA + e * STRIDE + j0;
#pragma unroll
        for (int q = 0; q < 16; q++) {
            float4 a = pa[q], b = pb[q], w = pw[q], bb = pb1[q];
            uint4 v;
            v.x = f2tf(silu(a.x + b.x + d * w.x + bb.x));
            v.y = f2tf(silu(a.y + b.y + d * w.y + bb.y));
            v.z = f2tf(silu(a.z + b.z + d * w.z + bb.z));
            v.w = f2tf(silu(a.w + b.w + d * w.w + bb.w));
            *(uint4*)(dst + q * 4) = v;
        }
    }
    __syncthreads();

    float acc[2][8][4];
    mma_tile(sA, sB, warpM, warpN, lane, 128, acc);   // D1 = U @ m_w2
    __syncthreads();   // everyone done reading sA/sB

    int l4 = lane >> 2, q2 = (lane & 3) * 2;
    // msg = silu(D1 + b2): write tf32 into sA for GEMM2, scatter fp32 into agg
#pragma unroll
    for (int mi = 0; mi < 2; mi++)
#pragma unroll
        for (int half = 0; half < 2; half++) {
            int e = warpM * 32 + mi * 16 + l4 + half * 8;
            int valid = sValid[e];
            int cn = sCol[e];
#pragma unroll
            for (int ni = 0; ni < 8; ni++) {
                int c = warpN * 64 + ni * 8 + q2;
                float m0 = silu(acc[mi][ni][half*2+0] + __ldg(b2 + c));
                float m1 = silu(acc[mi][ni][half*2+1] + __ldg(b2 + c + 1));
                uint2 t; t.x = f2tf(m0); t.y = f2tf(m1);
                *(uint2*)(sA + e * STRIDE + c) = t;
                if (valid) red2(agg + (size_t)cn * 128 + c, m0, m1);
            }
        }
    for (int idx = tid; idx < 16384; idx += 256) {   // sB = c_w1
        int k = idx >> 7, nn = idx & 127;
        sB[k * STRIDE + nn] = f2tf(Cw1[k * 128 + nn]);
    }
    __syncthreads();

    mma_tile(sA, sB, warpM, warpN, lane, 128, acc);   // D2 = msg @ c_w1

    // per-edge dot: sum_c silu(D2 + cb1[c]) * cw2[c]
    float p[2][2];
#pragma unroll
    for (int mi = 0; mi < 2; mi++)
#pragma unroll
        for (int half = 0; half < 2; half++) p[mi][half] = 0.0f;
#pragma unroll
    for (int ni = 0; ni < 8; ni++) {
        int c = warpN * 64 + ni * 8 + q2;
        float w0c = __ldg(cw2 + c), w1c2 = __ldg(cw2 + c + 1);
        float b0c = __ldg(cb1 + c), b1c = __ldg(cb1 + c + 1);
#pragma unroll
        for (int mi = 0; mi < 2; mi++)
#pragma unroll
            for (int half = 0; half < 2; half++)
                p[mi][half] += silu(acc[mi][ni][half*2+0] + b0c) * w0c
                             + silu(acc[mi][ni][half*2+1] + b1c) * w1c2;
    }
#pragma unroll
    for (int mi = 0; mi < 2; mi++)
#pragma unroll
        for (int half = 0; half < 2; half++) {
            p[mi][half] += __shfl_xor_sync(0xffffffffu, p[mi][half], 1);
            p[mi][half] += __shfl_xor_sync(0xffffffffu, p[mi][half], 2);
        }
    if ((lane & 3) == 0) {
#pragma unroll
        for (int mi = 0; mi < 2; mi++)
#pragma unroll
            for (int half = 0; half < 2; half++)
                atomicAdd(&sPart[warpM * 32 + mi * 16 + l4 + half * 8], p[mi][half]);
    }
    __syncthreads();

    if (tid < 128 && sValid[tid]) {
        float cm = tanhf(sPart[tid]);
        float f = __fdividef(cm, sDist[tid] + 1e-8f);
        int c = sCol[tid];
        red1(cupd + c*3 + 0, f * sRelx[tid]);
        red1(cupd + c*3 + 1, f * sRely[tid]);
        red1(cupd + c*3 + 2, f * sRelz[tid]);
    }
}

// ---------------- fused edge kernel (epsilon head) ----------------
__global__ __launch_bounds__(256) void edge_eps_mma(
    const int* __restrict__ eRow, const int* __restrict__ eCol, int E,
    const float* __restrict__ x,
    const float* __restrict__ hA, const float* __restrict__ hB,
    const float* __restrict__ wRel,   // em_w1 rows 256..259
    const float* __restrict__ b1,
    const float* __restrict__ W2, const float* __restrict__ b2,
    const float* __restrict__ Cw1, const float* __restrict__ cb1,
    const float* __restrict__ cw2,   // ec_w2 [128][3]
    const float* __restrict__ cb2,   // ec_b2 [3]
    float* __restrict__ eps)
{
    extern __shared__ char smem[];
    uint32_t* sA = (uint32_t*)smem;
    uint32_t* sB = (uint32_t*)(smem + SB_OFF);
    char* aux = smem + SMEM_AB;
    int*   sRow   = (int*)(aux);
    int*   sCol   = (int*)(aux + 512);
    int*   sValid = (int*)(aux + 1024);
    float* sDist  = (float*)(aux + 1536);
    float* sRelx  = (float*)(aux + 2048);
    float* sRely  = (float*)(aux + 2560);
    float* sRelz  = (float*)(aux + 3072);
    float* sPart  = (float*)(aux + 3584);   // 384 floats

    int tid = threadIdx.x, wid = tid >> 5, lane = tid & 31;
    int warpM = wid & 3, warpN = wid >> 2;
    int e0 = blockIdx.x * 128;

    for (int i = tid; i < 384; i += 256) sPart[i] = 0.0f;
    if (tid < 128) {
        int e = e0 + tid;
        int valid = (e < E); if (!valid) e = E - 1;
        int r = eRow[e], c = eCol[e];
        float rx = x[r*3]   - x[c*3];
        float ry = x[r*3+1] - x[c*3+1];
        float rz = x[r*3+2] - x[c*3+2];
        float d = sqrtf(rx*rx + ry*ry + rz*rz);
        sRow[tid] = r; sCol[tid] = c; sValid[tid] = valid;
        sDist[tid] = d; sRelx[tid] = rx; sRely[tid] = ry; sRelz[tid] = rz;
    }
    for (int idx = tid; idx < 16384; idx += 256) {
        int k = idx >> 7, nn = idx & 127;
        sB[k * STRIDE + nn] = f2tf(W2[k * 128 + nn]);
    }
    __syncthreads();

    {
        int e = tid >> 1, j0 = (tid & 1) * 64;
        int r = sRow[e], c = sCol[e];
        float d = sDist[e], rx = sRelx[e], ry = sRely[e], rz = sRelz[e];
        const float4* pa  = (const float4*)(hA + (size_t)r * 128 + j0);
        const float4* pb  = (const float4*)(hB + (size_t)c * 128 + j0);
        const float4* pwx = (const float4*)(wRel + j0);
        const float4* pwy = (const float4*)(wRel + 128 + j0);
        const float4* pwz = (const float4*)(wRel + 256 + j0);
        const float4* pwd = (const float4*)(wRel + 384 + j0);
        const float4* pb1 = (const float4*)(b1 + j0);
        uint32_t* dst = sA + e * STRIDE + j0;
#pragma unroll
        for (int q = 0; q < 16; q++) {
            float4 a = pa[q], b = pb[q];
            float4 wx = pwx[q], wy = pwy[q], wz = pwz[q], wd = pwd[q], bb = pb1[q];
            uint4 v;
            v.x = f2tf(silu(a.x + b.x + rx*wx.x + ry*wy.x + rz*wz.x + d*wd.x + bb.x));
            v.y = f2tf(silu(a.y + b.y + rx*wx.y + ry*wy.y + rz*wz.y + d*wd.y + bb.y));
            v.z = f2tf(silu(a.z + b.z + rx*wx.z + ry*wy.z + rz*wz.z + d*wd.z + bb.z));
            v.w = f2tf(silu(a.w + b.w + rx*wx.w + ry*wy.w + rz*wz.w + d*wd.w + bb.w));
            *(uint4*)(dst + q * 4) = v;
        }
    }
    __syncthreads();

    float acc[2][8][4];
    mma_tile(sA, sB, warpM, warpN, lane, 128, acc);
    __syncthreads();

    int l4 = lane >> 2, q2 = (lane & 3) * 2;
#pragma unroll
    for (int mi = 0; mi < 2; mi++)
#pragma unroll
        for (int half = 0; half < 2; half++) {
            int e = warpM * 32 + mi * 16 + l4 + half * 8;
#pragma unroll
            for (int ni = 0; ni < 8; ni++) {
                int c = warpN * 64 + ni * 8 + q2;
                uint2 t;
                t.x = f2tf(silu(acc[mi][ni][half*2+0] + __ldg(b2 + c)));
                t.y = f2tf(silu(acc[mi][ni][half*2+1] + __ldg(b2 + c + 1)));
                *(uint2*)(sA + e * STRIDE + c) = t;
            }
        }
    for (int idx = tid; idx < 16384; idx += 256) {
        int k = idx >> 7, nn = idx & 127;
        sB[k * STRIDE + nn] = f2tf(Cw1[k * 128 + nn]);
    }
    __syncthreads();

    mma_tile(sA, sB, warpM, warpN, lane, 128, acc);

    float p[2][2][3];
#pragma unroll
    for (int mi = 0; mi < 2; mi++)
#pragma unroll
        for (int half = 0; half < 2; half++)
            p[mi][half][0] = p[mi][half][1] = p[mi][half][2] = 0.0f;
#pragma unroll
    for (int ni = 0; ni < 8; ni++) {
        int c = warpN * 64 + ni * 8 + q2;
        float b0c = __ldg(cb1 + c), b1c = __ldg(cb1 + c + 1);
        float w00 = __ldg(cw2 + c*3+0), w01 = __ldg(cw2 + c*3+1), w02 = __ldg(cw2 + c*3+2);
        float w10 = __ldg(cw2 + c*3+3), w11 = __ldg(cw2 + c*3+4), w12 = __ldg(cw2 + c*3+5);
#pragma unroll
        for (int mi = 0; mi < 2; mi++)
#pragma unroll
            for (int half = 0; half < 2; half++) {
                float v0 = silu(acc[mi][ni][half*2+0] + b0c);
                float v1 = silu(acc[mi][ni][half*2+1] + b1c);
                p[mi][half][0] += v0*w00 + v1*w10;
                p[mi][half][1] += v0*w01 + v1*w11;
                p[mi][half][2] += v0*w02 + v1*w12;
            }
    }
#pragma unroll
    for (int mi = 0; mi < 2; mi++)
#pragma unroll
        for (int half = 0; half < 2; half++)
#pragma unroll
            for (int d = 0; d < 3; d++) {
                p[mi][half][d] += __shfl_xor_sync(0xffffffffu, p[mi][half][d], 1);
                p[mi][half][d] += __shfl_xor_sync(0xffffffffu, p[mi][half][d], 2);
            }
    if ((lane & 3) == 0) {
#pragma unroll
        for (int mi = 0; mi < 2; mi++)
#pragma unroll
            for (int half = 0; half < 2; half++) {
                int e = warpM * 32 + mi * 16 + l4 + half * 8;
                atomicAdd(&sPart[e*3 + 0], p[mi][half][0]);
                atomicAdd(&sPart[e*3 + 1], p[mi][half][1]);
                atomicAdd(&sPart[e*3 + 2], p[mi][half][2]);
            }
    }
    __syncthreads();

    if (tid < 128 && sValid[tid]) {
        int c = sCol[tid];
        red1(eps + c*3 + 0, sPart[tid*3 + 0] + __ldg(cb2 + 0));
        red1(eps + c*3 + 1, sPart[tid*3 + 1] + __ldg(cb2 + 1));
        red1(eps + c*3 + 2, sPart[tid*3 + 2] + __ldg(cb2 + 2));
    }
}

// ---------------- residual + LayerNorm + x update ----------------
__global__ __launch_bounds__(128) void ln_update(
    const float* __restrict__ v, const float* __restrict__ g, const float* __restrict__ b,
    float* __restrict__ h, float* __restrict__ x,
    const float* __restrict__ cupd, const float* __restrict__ deg)
{
    int node = blockIdx.x;
    int j = threadIdx.x;
    float val = h[(size_t)node*128 + j] + v[(size_t)node*128 + j];
    float s = val, s2 = val * val;
#pragma unroll
    for (int m = 16; m >= 1; m >>= 1) {
        s  += __shfl_xor_sync(0xffffffffu, s, m);
        s2 += __shfl_xor_sync(0xffffffffu, s2, m);
    }
    __shared__ float ws[4], ws2[4];
    int wid = j >> 5, lane = j & 31;
    if (lane == 0) { ws[wid] = s; ws2[wid] = s2; }
    __syncthreads();
    s  = ws[0] + ws[1] + ws[2] + ws[3];
    s2 = ws2[0] + ws2[1] + ws2[2] + ws2[3];
    float mu = s * (1.0f / 128.0f);
    float var = s2 * (1.0f / 128.0f) - mu * mu;
    float out = (val - mu) * rsqrtf(var + 1e-5f) * g[j] + b[j];
    h[(size_t)node*128 + j] = out;
    if (j < 3) x[node*3 + j] += cupd[node*3 + j] / (deg[node] + 1.0f);
}

// ---------------- eps node head (fuses x-projection) ----------------
__global__ void eps_final2(const float* __restrict__ t, const float* __restrict__ x,
                           const float* __restrict__ w1x3,  // eh_w1 rows 128..130
                           const float* __restrict__ b1,
                           const float* __restrict__ W2,    // eh_w2 [128][3]
                           const float* __restrict__ b2,
                           float* __restrict__ eps)
{
    int node = blockIdx.x;
    int tid = threadIdx.x;   // 96 threads
    int d = tid >> 5, lane = tid & 31;
    float x0 = x[node*3], x1 = x[node*3+1], x2 = x[node*3+2];
    float p = 0.0f;
    for (int k = lane; k < 128; k += 32) {
        float v = t[(size_t)node*128 + k] + x0*w1x3[k] + x1*w1x3[128+k] + x2*w1x3[256+k] + b1[k];
        p += silu(v) * W2[k*3 + d];
    }
#pragma unroll
    for (int m = 16; m >= 1; m >>= 1) p += __shfl_xor_sync(0xffffffffu, p, m);
    if (lane == 0) eps[node*3 + d] += p + b2[d];
}

// ---------------- pack output: [h | x | eps] ----------------
__global__ void pack_kernel(const float* __restrict__ h, const float* __restrict__ x,
                            const float* __restrict__ eps, float* __restrict__ out, int n)
{
    int i = blockIdx.x * blockDim.x + threadIdx.x;
    int nh = n * 128;
    if (i < nh) out[i] = h[i];
    else if (i < nh + 3*n) out[i] = x[i - nh];
    else if (i < nh + 6*n) out[i] = eps[i - nh - 3*n];
}

// ---------------- host ----------------
static const int NODE_SMEM = SMEM_AB;            // 139264
static const int EDGE_SMEM = SMEM_AB + 5120;     // 144384

extern "C" void kernel_launch(void* const* d_in, const int* in_sizes, int n_in,
                              void* d_out, int out_size)
{
    const float* in_h  = (const float*)d_in[0];
    const float* in_x  = (const float*)d_in[1];
    const int*   eidx  = (const int*)d_in[2];
    const float* emb_w = (const float*)d_in[3];
    const float* emb_b = (const float*)d_in[4];
    const float* m_w1  = (const float*)d_in[5];
    const float* m_b1  = (const float*)d_in[6];
    const float* m_w2  = (const float*)d_in[7];
    const float* m_b2  = (const float*)d_in[8];
    const float* c_w1  = (const float*)d_in[9];
    const float* c_b1  = (const float*)d_in[10];
    const float* c_w2  = (const float*)d_in[11];
    const float* n_w1  = (const float*)d_in[12];
    const float* n_b1  = (const float*)d_in[13];
    const float* n_w2  = (const float*)d_in[14];
    const float* n_b2  = (const float*)d_in[15];
    const float* ln_g  = (const float*)d_in[16];
    const float* ln_b  = (const float*)d_in[17];
    const float* em_w1 = (const float*)d_in[18];
    const float* em_b1 = (const float*)d_in[19];
    const float* em_w2 = (const float*)d_in[20];
    const float* em_b2 = (const float*)d_in[21];
    const float* ec_w1 = (const float*)d_in[22];
    const float* ec_b1 = (const float*)d_in[23];
    const float* ec_w2 = (const float*)d_in[24];
    const float* ec_b2 = (const float*)d_in[25];
    const float* eh_w1 = (const float*)d_in[26];
    const float* eh_b1 = (const float*)d_in[27];
    const float* eh_w2 = (const float*)d_in[28];
    const float* eh_b2 = (const float*)d_in[29];

    int n = in_sizes[0] / 64;
    int E = in_sizes[2] / 2;
    const int* eRow = eidx;
    const int* eCol = eidx + E;

    float *h, *x, *hA, *hB, *agg, *tmp, *v, *cup, *eps, *deg;
    cudaGetSymbolAddress((void**)&h,   g_h);
    cudaGetSymbolAddress((void**)&x,   g_x);
    cudaGetSymbolAddress((void**)&hA,  g_hA);
    cudaGetSymbolAddress((void**)&hB,  g_hB);
    cudaGetSymbolAddress((void**)&agg, g_agg);
    cudaGetSymbolAddress((void**)&tmp, g_tmp);
    cudaGetSymbolAddress((void**)&v,   g_v);
    cudaGetSymbolAddress((void**)&cup, g_cup);
    cudaGetSymbolAddress((void**)&eps, g_eps);
    cudaGetSymbolAddress((void**)&deg, g_deg);

    cudaFuncSetAttribute(gemm_mma,       cudaFuncAttributeMaxDynamicSharedMemorySize, NODE_SMEM);
    cudaFuncSetAttribute(edge_layer_mma, cudaFuncAttributeMaxDynamicSharedMemorySize, EDGE_SMEM);
    cudaFuncSetAttribute(edge_eps_mma,   cudaFuncAttributeMaxDynamicSharedMemorySize, EDGE_SMEM);

    int gN = (n + 127) / 128;
    int gE = (E + 127) / 128;

    zero_kernel<<<(n + 255)/256, 256>>>(deg, n);
    indeg_kernel<<<(E + 255)/256, 256>>>(eCol, E, deg);

    gemm_mma<<<gN, 256, NODE_SMEM>>>(in_h, 64, emb_w, emb_b, h, n, 0, 0);
    copy_kernel<<<(3*n + 255)/256, 256>>>(in_x, x, 3*n);

    for (int i = 0; i < 4; i++) {
        const float* w1 = m_w1 + (size_t)i*257*128;
        gemm_mma<<<gN, 256, NODE_SMEM>>>(h, 128, w1,           nullptr, hA, n, 0, 0);
        gemm_mma<<<gN, 256, NODE_SMEM>>>(h, 128, w1 + 128*128, nullptr, hB, n, 0, 0);
        zero_kernel<<<(n*128 + 255)/256, 256>>>(agg, n*128);
        zero_kernel<<<(3*n + 255)/256, 256>>>(cup, 3*n);
        edge_layer_mma<<<gE, 256, EDGE_SMEM>>>(
            eRow, eCol, E, x, hA, hB,
            w1 + 256*128, m_b1 + i*128,
            m_w2 + (size_t)i*128*128, m_b2 + i*128,
            c_w1 + (size_t)i*128*128, c_b1 + i*128, c_w2 + i*128,
            agg, cup);
        gemm_mma<<<gN, 256, NODE_SMEM>>>(h,   128, n_w1 + (size_t)i*256*128,           nullptr,      tmp, n, 0, 0);
        gemm_mma<<<gN, 256, NODE_SMEM>>>(agg, 128, n_w1 + (size_t)i*256*128 + 128*128, n_b1 + i*128, tmp, n, 1, 1);
        gemm_mma<<<gN, 256, NODE_SMEM>>>(tmp, 128, n_w2 + (size_t)i*128*128,           n_b2 + i*128, v,   n, 0, 0);
        ln_update<<<n, 128>>>(v, ln_g + i*128, ln_b + i*128, h, x, cup, deg);
    }

    gemm_mma<<<gN, 256, NODE_SMEM>>>(h, 128, em_w1,           nullptr, hA, n, 0, 0);
    gemm_mma<<<gN, 256, NODE_SMEM>>>(h, 128, em_w1 + 128*128, nullptr, hB, n, 0, 0);
    zero_kernel<<<(3*n + 255)/256, 256>>>(eps, 3*n);
    edge_eps_mma<<<gE, 256, EDGE_SMEM>>>(
        eRow, eCol, E, x, hA, hB,
        em_w1 + 256*128, em_b1,
        em_w2, em_b2, ec_w1, ec_b1, ec_w2, ec_b2, eps);
    gemm_mma<<<gN, 256, NODE_SMEM>>>(h, 128, eh_w1, nullptr, tmp, n, 0, 0);
    eps_final2<<<n, 96>>>(tmp, x, eh_w1 + 128*128, eh_b1, eh_w2, eh_b2, eps);

    pack_kernel<<<(n*134 + 255)/256, 256>>>(h, x, eps, (float*)d_out, n);
}

// round 5
// speedup vs baseline: 2.0688x; 1.2554x over previous
#include <cuda_runtime.h>
#include <math.h>
#include <stdint.h>

#define MAXN 50048
typedef unsigned long long u64;

// ---------------- scratch (static device arrays; no cudaMalloc) ----------------
__device__ float g_h  [MAXN*128];
__device__ float g_x  [MAXN*3];
__device__ float g_hA [MAXN*128];
__device__ float g_hB [MAXN*128];
__device__ float g_agg[MAXN*128];
__device__ float g_tmp[MAXN*128];
__device__ float g_v  [MAXN*128];
__device__ float g_cup[MAXN*3];
__device__ float g_eps[MAXN*3];
__device__ float g_deg[MAXN];

// ---------------- helpers ----------------
__device__ __forceinline__ float tanh_ap(float x) {
    float t; asm("tanh.approx.f32 %0,%1;" : "=f"(t) : "f"(x)); return t;
}
// silu(x) = x * sigmoid(x) = 0.5*x*(1 + tanh(x/2)) — one MUFU
__device__ __forceinline__ float silu(float x) {
    return 0.5f * x * (1.0f + tanh_ap(0.5f * x));
}
__device__ __forceinline__ uint32_t f2tf(float f) {
    uint32_t r; asm("cvt.rna.tf32.f32 %0, %1;" : "=r"(r) : "f"(f)); return r;
}
__device__ __forceinline__ void mma8(float d[4], uint32_t a0, uint32_t a1, uint32_t a2, uint32_t a3,
                                     uint32_t b0, uint32_t b1) {
    asm volatile(
        "mma.sync.aligned.m16n8k8.row.col.f32.tf32.tf32.f32 "
        "{%0,%1,%2,%3},{%4,%5,%6,%7},{%8,%9},{%0,%1,%2,%3};"
        : "+f"(d[0]), "+f"(d[1]), "+f"(d[2]), "+f"(d[3])
        : "r"(a0), "r"(a1), "r"(a2), "r"(a3), "r"(b0), "r"(b1));
}
__device__ __forceinline__ void red2(float* p, float a, float b) {
    asm volatile("red.global.add.v2.f32 [%0],{%1,%2};" :: "l"(p), "f"(a), "f"(b) : "memory");
}
__device__ __forceinline__ void red1(float* p, float a) {
    asm volatile("red.global.add.f32 [%0],%1;" :: "l"(p), "f"(a) : "memory");
}

#define STRIDE 136
#define SA_BYTES (128*STRIDE*4)   // 69632
#define SB_BYTES (64*STRIDE*4)    // 34816
#define SB_OFF   SA_BYTES
#define SMEM_AB  (SA_BYTES + SB_BYTES)   // 104448

// one K-half (64 k) of the warp-tile MMA. sA cols [kbase, kbase+64), sB rows 0..63.
__device__ __forceinline__ void mma_half(const uint32_t* __restrict__ sA,
                                         const uint32_t* __restrict__ sB,
                                         int warpM, int warpN, int lane, int kbase,
                                         float acc[2][8][4]) {
    int l4 = lane >> 2, lq = lane & 3;
    int rb = warpM * 32 + l4;
    int nb = warpN * 64 + l4;
#pragma unroll
    for (int kk = 0; kk < 64; kk += 8) {
        int k0 = kbase + kk;
        uint32_t a[2][4];
#pragma unroll
        for (int mi = 0; mi < 2; mi++) {
            int r = rb + mi * 16;
            a[mi][0] = sA[(r    ) * STRIDE + k0 + lq];
            a[mi][1] = sA[(r + 8) * STRIDE + k0 + lq];
            a[mi][2] = sA[(r    ) * STRIDE + k0 + lq + 4];
            a[mi][3] = sA[(r + 8) * STRIDE + k0 + lq + 4];
        }
#pragma unroll
        for (int ni = 0; ni < 8; ni++) {
            int n = nb + ni * 8;
            uint32_t b0 = sB[(kk + lq    ) * STRIDE + n];
            uint32_t b1 = sB[(kk + lq + 4) * STRIDE + n];
            mma8(acc[0][ni], a[0][0], a[0][1], a[0][2], a[0][3], b0, b1);
            mma8(acc[1][ni], a[1][0], a[1][1], a[1][2], a[1][3], b0, b1);
        }
    }
}
__device__ __forceinline__ void acc_zero(float acc[2][8][4]) {
#pragma unroll
    for (int mi = 0; mi < 2; mi++)
#pragma unroll
        for (int ni = 0; ni < 8; ni++)
#pragma unroll
            for (int j = 0; j < 4; j++) acc[mi][ni][j] = 0.0f;
}
// load 64 k-rows of W (row-major [k][128]) into sB as tf32
__device__ __forceinline__ void load_B_half(uint32_t* sB, const float* __restrict__ W,
                                            int kbase, int tid) {
    for (int idx = tid; idx < 8192; idx += 256) {
        int k = idx >> 7, nn = idx & 127;
        sB[k * STRIDE + nn] = f2tf(W[(kbase + k) * 128 + nn]);
    }
}

// ---------------- small utility kernels ----------------
__global__ void zero_kernel(float* p, int n) {
    int i = blockIdx.x * blockDim.x + threadIdx.x;
    if (i < n) p[i] = 0.0f;
}
__global__ void copy_kernel(const float* __restrict__ s, float* d, int n) {
    int i = blockIdx.x * blockDim.x + threadIdx.x;
    if (i < n) d[i] = s[i];
}
__global__ void indeg_kernel(const int* __restrict__ col, int E, float* deg) {
    int i = blockIdx.x * blockDim.x + threadIdx.x;
    if (i < E) atomicAdd(&deg[col[i]], 1.0f);
}

// ---------------- node GEMM (tf32 mma, staged B): out = act(beta*out + A@W + bias) ----------------
__global__ __launch_bounds__(256, 2) void gemm_mma(
    const float* __restrict__ A, int K,
    const float* __restrict__ W,
    const float* __restrict__ bias,
    float* __restrict__ out, int n, int beta, int act)
{
    extern __shared__ char smem[];
    uint32_t* sA = (uint32_t*)smem;
    uint32_t* sB = (uint32_t*)(smem + SB_OFF);
    int tid = threadIdx.x, wid = tid >> 5, lane = tid & 31;
    int warpM = wid & 3, warpN = wid >> 2;
    int m0 = blockIdx.x * 128;

    if (K == 128) {
        for (int idx = tid; idx < 16384; idx += 256) {
            int m = idx >> 7, k = idx & 127;
            int gm = m0 + m; if (gm >= n) gm = n - 1;
            sA[m * STRIDE + k] = f2tf(A[(size_t)gm * 128 + k]);
        }
    } else {  // K == 64
        for (int idx = tid; idx < 8192; idx += 256) {
            int m = idx >> 6, k = idx & 63;
            int gm = m0 + m; if (gm >= n) gm = n - 1;
            sA[m * STRIDE + k] = f2tf(A[(size_t)gm * 64 + k]);
        }
    }
    load_B_half(sB, W, 0, tid);
    __syncthreads();

    float acc[2][8][4];
    acc_zero(acc);
    mma_half(sA, sB, warpM, warpN, lane, 0, acc);
    if (K == 128) {
        __syncthreads();
        load_B_half(sB, W, 64, tid);
        __syncthreads();
        mma_half(sA, sB, warpM, warpN, lane, 64, acc);
    }

    int l4 = lane >> 2, q2 = (lane & 3) * 2;
    float2 bv[8];
#pragma unroll
    for (int ni = 0; ni < 8; ni++) {
        int c = warpN * 64 + ni * 8 + q2;
        bv[ni] = bias ? *(const float2*)(bias + c) : make_float2(0.0f, 0.0f);
    }
#pragma unroll
    for (int mi = 0; mi < 2; mi++)
#pragma unroll
        for (int half = 0; half < 2; half++) {
            int gm = m0 + warpM * 32 + mi * 16 + l4 + half * 8;
            if (gm >= n) continue;
            float* orow = out + (size_t)gm * 128;
#pragma unroll
            for (int ni = 0; ni < 8; ni++) {
                int c = warpN * 64 + ni * 8 + q2;
                float v0 = acc[mi][ni][half * 2 + 0] + bv[ni].x;
                float v1 = acc[mi][ni][half * 2 + 1] + bv[ni].y;
                if (beta) { float2 o = *(float2*)(orow + c); v0 += o.x; v1 += o.y; }
                if (act)  { v0 = silu(v0); v1 = silu(v1); }
                *(float2*)(orow + c) = make_float2(v0, v1);
            }
        }
}

// ---------------- fused edge kernel (message-passing layer) ----------------
__global__ __launch_bounds__(256, 2) void edge_layer_mma(
    const int* __restrict__ eRow, const int* __restrict__ eCol, int E,
    const float* __restrict__ x,
    const float* __restrict__ hA, const float* __restrict__ hB,
    const float* __restrict__ w1c, const float* __restrict__ b1,
    const float* __restrict__ W2, const float* __restrict__ b2,
    const float* __restrict__ Cw1, const float* __restrict__ cb1,
    const float* __restrict__ cw2,
    float* __restrict__ agg, float* __restrict__ cupd)
{
    extern __shared__ char smem[];
    uint32_t* sA = (uint32_t*)smem;
    uint32_t* sB = (uint32_t*)(smem + SB_OFF);
    char* aux = smem + SMEM_AB;
    int*   sRow   = (int*)(aux);
    int*   sCol   = (int*)(aux + 512);
    int*   sValid = (int*)(aux + 1024);
    float* sDist  = (float*)(aux + 1536);
    float* sRelx  = (float*)(aux + 2048);
    float* sRely  = (float*)(aux + 2560);
    float* sRelz  = (float*)(aux + 3072);
    float* sPart  = (float*)(aux + 3584);

    int tid = threadIdx.x, wid = tid >> 5, lane = tid & 31;
    int warpM = wid & 3, warpN = wid >> 2;
    int e0 = blockIdx.x * 128;

    if (tid < 128) {
        sPart[tid] = 0.0f;
        int e = e0 + tid;
        int valid = (e < E); if (!valid) e = E - 1;
        int r = eRow[e], c = eCol[e];
        float rx = x[r*3]   - x[c*3];
        float ry = x[r*3+1] - x[c*3+1];
        float rz = x[r*3+2] - x[c*3+2];
        float d = sqrtf(rx*rx + ry*ry + rz*rz);
        sRow[tid] = r; sCol[tid] = c; sValid[tid] = valid;
        sDist[tid] = d; sRelx[tid] = rx; sRely[tid] = ry; sRelz[tid] = rz;
    }
    load_B_half(sB, W2, 0, tid);
    __syncthreads();

    {   // sA[e][k] = silu(t1), two threads per edge
        int e = tid >> 1, j0 = (tid & 1) * 64;
        int r = sRow[e], c = sCol[e];
        float d = sDist[e];
        const float4* pa  = (const float4*)(hA  + (size_t)r * 128 + j0);
        const float4* pb  = (const float4*)(hB  + (size_t)c * 128 + j0);
        const float4* pw  = (const float4*)(w1c + j0);
        const float4* pb1 = (const float4*)(b1  + j0);
        uint32_t* dst = sA + e * STRIDE + j0;
#pragma unroll
        for (int q = 0; q < 16; q++) {
            float4 a = pa[q], b = pb[q], w = pw[q], bb = pb1[q];
            uint4 v;
            v.x = f2tf(silu(a.x + b.x + d * w.x + bb.x));
            v.y = f2tf(silu(a.y + b.y + d * w.y + bb.y));
            v.z = f2tf(silu(a.z + b.z + d * w.z + bb.z));
            v.w = f2tf(silu(a.w + b.w + d * w.w + bb.w));
            *(uint4*)(dst + q * 4) = v;
        }
    }
    __syncthreads();

    float acc[2][8][4];
    acc_zero(acc);
    mma_half(sA, sB, warpM, warpN, lane, 0, acc);     // D1 += U[:,0:64] @ W2[0:64,:]
    __syncthreads();
    load_B_half(sB, W2, 64, tid);
    __syncthreads();
    mma_half(sA, sB, warpM, warpN, lane, 64, acc);    // D1 += U[:,64:128] @ W2[64:128,:]
    __syncthreads();   // all warps done reading sA/sB

    int l4 = lane >> 2, q2 = (lane & 3) * 2;
    {   // msg = silu(D1 + b2): tf32 into sA for GEMM2, fp32 scatter into agg
        float2 bv[8];
#pragma unroll
        for (int ni = 0; ni < 8; ni++) bv[ni] = *(const float2*)(b2 + warpN * 64 + ni * 8 + q2);
#pragma unroll
        for (int mi = 0; mi < 2; mi++)
#pragma unroll
            for (int half = 0; half < 2; half++) {
                int e = warpM * 32 + mi * 16 + l4 + half * 8;
                int valid = sValid[e];
                int cn = sCol[e];
#pragma unroll
                for (int ni = 0; ni < 8; ni++) {
                    int c = warpN * 64 + ni * 8 + q2;
                    float m0 = silu(acc[mi][ni][half*2+0] + bv[ni].x);
                    float m1 = silu(acc[mi][ni][half*2+1] + bv[ni].y);
                    uint2 t; t.x = f2tf(m0); t.y = f2tf(m1);
                    *(uint2*)(sA + e * STRIDE + c) = t;
                    if (valid) red2(agg + (size_t)cn * 128 + c, m0, m1);
                }
            }
    }
    load_B_half(sB, Cw1, 0, tid);
    __syncthreads();

    acc_zero(acc);
    mma_half(sA, sB, warpM, warpN, lane, 0, acc);
    __syncthreads();
    load_B_half(sB, Cw1, 64, tid);
    __syncthreads();
    mma_half(sA, sB, warpM, warpN, lane, 64, acc);    // D2 = msg @ c_w1

    // per-edge dot: sum_c silu(D2 + cb1[c]) * cw2[c]
    float2 cbv[8], cwv[8];
#pragma unroll
    for (int ni = 0; ni < 8; ni++) {
        int c = warpN * 64 + ni * 8 + q2;
        cbv[ni] = *(const float2*)(cb1 + c);
        cwv[ni] = *(const float2*)(cw2 + c);
    }
    float p[2][2];
    p[0][0] = p[0][1] = p[1][0] = p[1][1] = 0.0f;
#pragma unroll
    for (int ni = 0; ni < 8; ni++)
#pragma unroll
        for (int mi = 0; mi < 2; mi++)
#pragma unroll
            for (int half = 0; half < 2; half++)
                p[mi][half] += silu(acc[mi][ni][half*2+0] + cbv[ni].x) * cwv[ni].x
                             + silu(acc[mi][ni][half*2+1] + cbv[ni].y) * cwv[ni].y;
#pragma unroll
    for (int mi = 0; mi < 2; mi++)
#pragma unroll
        for (int half = 0; half < 2; half++) {
            p[mi][half] += __shfl_xor_sync(0xffffffffu, p[mi][half], 1);
            p[mi][half] += __shfl_xor_sync(0xffffffffu, p[mi][half], 2);
        }
    if ((lane & 3) == 0) {
#pragma unroll
        for (int mi = 0; mi < 2; mi++)
#pragma unroll
            for (int half = 0; half < 2; half++)
                atomicAdd(&sPart[warpM * 32 + mi * 16 + l4 + half * 8], p[mi][half]);
    }
    __syncthreads();

    if (tid < 128 && sValid[tid]) {
        float cm = tanh_ap(sPart[tid]);
        float f = __fdividef(cm, sDist[tid] + 1e-8f);
        int c = sCol[tid];
        red1(cupd + c*3 + 0, f * sRelx[tid]);
        red1(cupd + c*3 + 1, f * sRely[tid]);
        red1(cupd + c*3 + 2, f * sRelz[tid]);
    }
}

// ---------------- fused edge kernel (epsilon head) ----------------
__global__ __launch_bounds__(256, 2) void edge_eps_mma(
    const int* __restrict__ eRow, const int* __restrict__ eCol, int E,
    const float* __restrict__ x,
    const float* __restrict__ hA, const float* __restrict__ hB,
    const float* __restrict__ wRel,   // em_w1 rows 256..259
    const float* __restrict__ b1,
    const float* __restrict__ W2, const float* __restrict__ b2,
    const float* __restrict__ Cw1, const float* __restrict__ cb1,
    const float* __restrict__ cw2,   // ec_w2 [128][3]
    const float* __restrict__ cb2,   // ec_b2 [3]
    float* __restrict__ eps)
{
    extern __shared__ char smem[];
    uint32_t* sA = (uint32_t*)smem;
    uint32_t* sB = (uint32_t*)(smem + SB_OFF);
    char* aux = smem + SMEM_AB;
    int*   sRow   = (int*)(aux);
    int*   sCol   = (int*)(aux + 512);
    int*   sValid = (int*)(aux + 1024);
    float* sDist  = (float*)(aux + 1536);
    float* sRelx  = (float*)(aux + 2048);
    float* sRely  = (float*)(aux + 2560);
    float* sRelz  = (float*)(aux + 3072);
    float* sPart  = (float*)(aux + 3584);   // 384 floats

    int tid = threadIdx.x, wid = tid >> 5, lane = tid & 31;
    int warpM = wid & 3, warpN = wid >> 2;
    int e0 = blockIdx.x * 128;

    for (int i = tid; i < 384; i += 256) sPart[i] = 0.0f;
    if (tid < 128) {
        int e = e0 + tid;
        int valid = (e < E); if (!valid) e = E - 1;
        int r = eRow[e], c = eCol[e];
        float rx = x[r*3]   - x[c*3];
        float ry = x[r*3+1] - x[c*3+1];
        float rz = x[r*3+2] - x[c*3+2];
        float d = sqrtf(rx*rx + ry*ry + rz*rz);
        sRow[tid] = r; sCol[tid] = c; sValid[tid] = valid;
        sDist[tid] = d; sRelx[tid] = rx; sRely[tid] = ry; sRelz[tid] = rz;
    }
    load_B_half(sB, W2, 0, tid);
    __syncthreads();

    {
        int e = tid >> 1, j0 = (tid & 1) * 64;
        int r = sRow[e], c = sCol[e];
        float d = sDist[e], rx = sRelx[e], ry = sRely[e], rz = sRelz[e];
        const float4* pa  = (const float4*)(hA + (size_t)r * 128 + j0);
        const float4* pb  = (const float4*)(hB + (size_t)c * 128 + j0);
        const float4* pwx = (const float4*)(wRel + j0);
        const float4* pwy = (const float4*)(wRel + 128 + j0);
        const float4* pwz = (const float4*)(wRel + 256 + j0);
        const float4* pwd = (const float4*)(wRel + 384 + j0);
        const float4* pb1 = (const float4*)(b1 + j0);
        uint32_t* dst = sA + e * STRIDE + j0;
#pragma unroll
        for (int q = 0; q < 16; q++) {
            float4 a = pa[q], b = pb[q];
            float4 wx = pwx[q], wy = pwy[q], wz = pwz[q], wd = pwd[q], bb = pb1[q];
            uint4 v;
            v.x = f2tf(silu(a.x + b.x + rx*wx.x + ry*wy.x + rz*wz.x + d*wd.x + bb.x));
            v.y = f2tf(silu(a.y + b.y + rx*wx.y + ry*wy.y + rz*wz.y + d*wd.y + bb.y));
            v.z = f2tf(silu(a.z + b.z + rx*wx.z + ry*wy.z + rz*wz.z + d*wd.z + bb.z));
            v.w = f2tf(silu(a.w + b.w + rx*wx.w + ry*wy.w + rz*wz.w + d*wd.w + bb.w));
            *(uint4*)(dst + q * 4) = v;
        }
    }
    __syncthreads();

    float acc[2][8][4];
    acc_zero(acc);
    mma_half(sA, sB, warpM, warpN, lane, 0, acc);
    __syncthreads();
    load_B_half(sB, W2, 64, tid);
    __syncthreads();
    mma_half(sA, sB, warpM, warpN, lane, 64, acc);
    __syncthreads();

    int l4 = lane >> 2, q2 = (lane & 3) * 2;
    {
        float2 bv[8];
#pragma unroll
        for (int ni = 0; ni < 8; ni++) bv[ni] = *(const float2*)(b2 + warpN * 64 + ni * 8 + q2);
#pragma unroll
        for (int mi = 0; mi < 2; mi++)
#pragma unroll
            for (int half = 0; half < 2; half++) {
                int e = warpM * 32 + mi * 16 + l4 + half * 8;
#pragma unroll
                for (int ni = 0; ni < 8; ni++) {
                    int c = warpN * 64 + ni * 8 + q2;
                    uint2 t;
                    t.x = f2tf(silu(acc[mi][ni][half*2+0] + bv[ni].x));
                    t.y = f2tf(silu(acc[mi][ni][half*2+1] + bv[ni].y));
                    *(uint2*)(sA + e * STRIDE + c) = t;
                }
            }
    }
    load_B_half(sB, Cw1, 0, tid);
    __syncthreads();

    acc_zero(acc);
    mma_half(sA, sB, warpM, warpN, lane, 0, acc);
    __syncthreads();
    load_B_half(sB, Cw1, 64, tid);
    __syncthreads();
    mma_half(sA, sB, warpM, warpN, lane, 64, acc);

    float p[2][2][3];
#pragma unroll
    for (int mi = 0; mi < 2; mi++)
#pragma unroll
        for (int half = 0; half < 2; half++)
            p[mi][half][0] = p[mi][half][1] = p[mi][half][2] = 0.0f;
#pragma unroll
    for (int ni = 0; ni < 8; ni++) {
        int c = warpN * 64 + ni * 8 + q2;
        float2 cbv = *(const float2*)(cb1 + c);
        float w00 = cw2[c*3+0], w01 = cw2[c*3+1], w02 = cw2[c*3+2];
        float w10 = cw2[c*3+3], w11 = cw2[c*3+4], w12 = cw2[c*3+5];
#pragma unroll
        for (int mi = 0; mi < 2; mi++)
#pragma unroll
            for (int half = 0; half < 2; half++) {
                float v0 = silu(acc[mi][ni][half*2+0] + cbv.x);
                float v1 = silu(acc[mi][ni][half*2+1] + cbv.y);
                p[mi][half][0] += v0*w00 + v1*w10;
                p[mi][half][1] += v0*w01 + v1*w11;
                p[mi][half][2] += v0*w02 + v1*w12;
            }
    }
#pragma unroll
    for (int mi = 0; mi < 2; mi++)
#pragma unroll
        for (int half = 0; half < 2; half++)
#pragma unroll
            for (int d = 0; d < 3; d++) {
                p[mi][half][d] += __shfl_xor_sync(0xffffffffu, p[mi][half][d], 1);
                p[mi][half][d] += __shfl_xor_sync(0xffffffffu, p[mi][half][d], 2);
            }
    if ((lane & 3) == 0) {
#pragma unroll
        for (int mi = 0; mi < 2; mi++)
#pragma unroll
            for (int half = 0; half < 2; half++) {
                int e = warpM * 32 + mi * 16 + l4 + half * 8;
                atomicAdd(&sPart[e*3 + 0], p[mi][half][0]);
                atomicAdd(&sPart[e*3 + 1], p[mi][half][1]);
                atomicAdd(&sPart[e*3 + 2], p[mi][half][2]);
            }
    }
    __syncthreads();

    if (tid < 128 && sValid[tid]) {
        int c = sCol[tid];
        red1(eps + c*3 + 0, sPart[tid*3 + 0] + cb2[0]);
        red1(eps + c*3 + 1, sPart[tid*3 + 1] + cb2[1]);
        red1(eps + c*3 + 2, sPart[tid*3 + 2] + cb2[2]);
    }
}

// ---------------- residual + LayerNorm + x update ----------------
__global__ __launch_bounds__(128) void ln_update(
    const float* __restrict__ v, const float* __restrict__ g, const float* __restrict__ b,
    float* __restrict__ h, float* __restrict__ x,
    const float* __restrict__ cupd, const float* __restrict__ deg)
{
    int node = blockIdx.x;
    int j = threadIdx.x;
    float val = h[(size_t)node*128 + j] + v[(size_t)node*128 + j];
    float s = val, s2 = val * val;
#pragma unroll
    for (int m = 16; m >= 1; m >>= 1) {
        s  += __shfl_xor_sync(0xffffffffu, s, m);
        s2 += __shfl_xor_sync(0xffffffffu, s2, m);
    }
    __shared__ float ws[4], ws2[4];
    int wid = j >> 5, lane = j & 31;
    if (lane == 0) { ws[wid] = s; ws2[wid] = s2; }
    __syncthreads();
    s  = ws[0] + ws[1] + ws[2] + ws[3];
    s2 = ws2[0] + ws2[1] + ws2[2] + ws2[3];
    float mu = s * (1.0f / 128.0f);
    float var = s2 * (1.0f / 128.0f) - mu * mu;
    float out = (val - mu) * rsqrtf(var + 1e-5f) * g[j] + b[j];
    h[(size_t)node*128 + j] = out;
    if (j < 3) x[node*3 + j] += cupd[node*3 + j] / (deg[node] + 1.0f);
}

// ---------------- eps node head (fuses x-projection) ----------------
__global__ void eps_final2(const float* __restrict__ t, const float* __restrict__ x,
                           const float* __restrict__ w1x3,  // eh_w1 rows 128..130
                           const float* __restrict__ b1,
                           const float* __restrict__ W2,    // eh_w2 [128][3]
                           const float* __restrict__ b2,
                           float* __restrict__ eps)
{
    int node = blockIdx.x;
    int tid = threadIdx.x;   // 96 threads
    int d = tid >> 5, lane = tid & 31;
    float x0 = x[node*3], x1 = x[node*3+1], x2 = x[node*3+2];
    float p = 0.0f;
    for (int k = lane; k < 128; k += 32) {
        float v = t[(size_t)node*128 + k] + x0*w1x3[k] + x1*w1x3[128+k] + x2*w1x3[256+k] + b1[k];
        p += silu(v) * W2[k*3 + d];
    }
#pragma unroll
    for (int m = 16; m >= 1; m >>= 1) p += __shfl_xor_sync(0xffffffffu, p, m);
    if (lane == 0) eps[node*3 + d] += p + b2[d];
}

// ---------------- pack output: [h | x | eps] ----------------
__global__ void pack_kernel(const float* __restrict__ h, const float* __restrict__ x,
                            const float* __restrict__ eps, float* __restrict__ out, int n)
{
    int i = blockIdx.x * blockDim.x + threadIdx.x;
    int nh = n * 128;
    if (i < nh) out[i] = h[i];
    else if (i < nh + 3*n) out[i] = x[i - nh];
    else if (i < nh + 6*n) out[i] = eps[i - nh - 3*n];
}

// ---------------- host ----------------
static const int NODE_SMEM = SMEM_AB;            // 104448
static const int EDGE_SMEM = SMEM_AB + 5120;     // 109568

extern "C" void kernel_launch(void* const* d_in, const int* in_sizes, int n_in,
                              void* d_out, int out_size)
{
    const float* in_h  = (const float*)d_in[0];
    const float* in_x  = (const float*)d_in[1];
    const int*   eidx  = (const int*)d_in[2];
    const float* emb_w = (const float*)d_in[3];
    const float* emb_b = (const float*)d_in[4];
    const float* m_w1  = (const float*)d_in[5];
    const float* m_b1  = (const float*)d_in[6];
    const float* m_w2  = (const float*)d_in[7];
    const float* m_b2  = (const float*)d_in[8];
    const float* c_w1  = (const float*)d_in[9];
    const float* c_b1  = (const float*)d_in[10];
    const float* c_w2  = (const float*)d_in[11];
    const float* n_w1  = (const float*)d_in[12];
    const float* n_b1  = (const float*)d_in[13];
    const float* n_w2  = (const float*)d_in[14];
    const float* n_b2  = (const float*)d_in[15];
    const float* ln_g  = (const float*)d_in[16];
    const float* ln_b  = (const float*)d_in[17];
    const float* em_w1 = (const float*)d_in[18];
    const float* em_b1 = (const float*)d_in[19];
    const float* em_w2 = (const float*)d_in[20];
    const float* em_b2 = (const float*)d_in[21];
    const float* ec_w1 = (const float*)d_in[22];
    const float* ec_b1 = (const float*)d_in[23];
    const float* ec_w2 = (const float*)d_in[24];
    const float* ec_b2 = (const float*)d_in[25];
    const float* eh_w1 = (const float*)d_in[26];
    const float* eh_b1 = (const float*)d_in[27];
    const float* eh_w2 = (const float*)d_in[28];
    const float* eh_b2 = (const float*)d_in[29];

    int n = in_sizes[0] / 64;
    int E = in_sizes[2] / 2;
    const int* eRow = eidx;
    const int* eCol = eidx + E;

    float *h, *x, *hA, *hB, *agg, *tmp, *v, *cup, *eps, *deg;
    cudaGetSymbolAddress((void**)&h,   g_h);
    cudaGetSymbolAddress((void**)&x,   g_x);
    cudaGetSymbolAddress((void**)&hA,  g_hA);
    cudaGetSymbolAddress((void**)&hB,  g_hB);
    cudaGetSymbolAddress((void**)&agg, g_agg);
    cudaGetSymbolAddress((void**)&tmp, g_tmp);
    cudaGetSymbolAddress((void**)&v,   g_v);
    cudaGetSymbolAddress((void**)&cup, g_cup);
    cudaGetSymbolAddress((void**)&eps, g_eps);
    cudaGetSymbolAddress((void**)&deg, g_deg);

    cudaFuncSetAttribute(gemm_mma,       cudaFuncAttributeMaxDynamicSharedMemorySize, NODE_SMEM);
    cudaFuncSetAttribute(edge_layer_mma, cudaFuncAttributeMaxDynamicSharedMemorySize, EDGE_SMEM);
    cudaFuncSetAttribute(edge_eps_mma,   cudaFuncAttributeMaxDynamicSharedMemorySize, EDGE_SMEM);

    int gN = (n + 127) / 128;
    int gE = (E + 127) / 128;

    zero_kernel<<<(n + 255)/256, 256>>>(deg, n);
    indeg_kernel<<<(E + 255)/256, 256>>>(eCol, E, deg);

    gemm_mma<<<gN, 256, NODE_SMEM>>>(in_h, 64, emb_w, emb_b, h, n, 0, 0);
    copy_kernel<<<(3*n + 255)/256, 256>>>(in_x, x, 3*n);

    for (int i = 0; i < 4; i++) {
        const float* w1 = m_w1 + (size_t)i*257*128;
        gemm_mma<<<gN, 256, NODE_SMEM>>>(h, 128, w1,           nullptr, hA, n, 0, 0);
        gemm_mma<<<gN, 256, NODE_SMEM>>>(h, 128, w1 + 128*128, nullptr, hB, n, 0, 0);
        zero_kernel<<<(n*128 + 255)/256, 256>>>(agg, n*128);
        zero_kernel<<<(3*n + 255)/256, 256>>>(cup, 3*n);
        edge_layer_mma<<<gE, 256, EDGE_SMEM>>>(
            eRow, eCol, E, x, hA, hB,
            w1 + 256*128, m_b1 + i*128,
            m_w2 + (size_t)i*128*128, m_b2 + i*128,
            c_w1 + (size_t)i*128*128, c_b1 + i*128, c_w2 + i*128,
            agg, cup);
        gemm_mma<<<gN, 256, NODE_SMEM>>>(h,   128, n_w1 + (size_t)i*256*128,           nullptr,      tmp, n, 0, 0);
        gemm_mma<<<gN, 256, NODE_SMEM>>>(agg, 128, n_w1 + (size_t)i*256*128 + 128*128, n_b1 + i*128, tmp, n, 1, 1);
        gemm_mma<<<gN, 256, NODE_SMEM>>>(tmp, 128, n_w2 + (size_t)i*128*128,           n_b2 + i*128, v,   n, 0, 0);
        ln_update<<<n, 128>>>(v, ln_g + i*128, ln_b + i*128, h, x, cup, deg);
    }

    gemm_mma<<<gN, 256, NODE_SMEM>>>(h, 128, em_w1,           nullptr, hA, n, 0, 0);
    gemm_mma<<<gN, 256, NODE_SMEM>>>(h, 128, em_w1 + 128*128, nullptr, hB, n, 0, 0);
    zero_kernel<<<(3*n + 255)/256, 256>>>(eps, 3*n);
    edge_eps_mma<<<gE, 256, EDGE_SMEM>>>(
        eRow, eCol, E, x, hA, hB,
        em_w1 + 256*128, em_b1,
        em_w2, em_b2, ec_w1, ec_b1, ec_w2, ec_b2, eps);
    gemm_mma<<<gN, 256, NODE_SMEM>>>(h, 128, eh_w1, nullptr, tmp, n, 0, 0);
    eps_final2<<<n, 96>>>(tmp, x, eh_w1 + 128*128, eh_b1, eh_w2, eh_b2, eps);

    pack_kernel<<<(n*134 + 255)/256, 256>>>(h, x, eps, (float*)d_out, n);
}

// round 6
// speedup vs baseline: 2.4365x; 1.1777x over previous
#include <cuda_runtime.h>
#include <math.h>
#include <stdint.h>

#define MAXN 50048
typedef unsigned long long u64;

// ---------------- scratch (static device arrays; no cudaMalloc) ----------------
__device__ float g_h  [MAXN*128];
__device__ float g_x  [MAXN*3];
__device__ float g_hA [MAXN*128];
__device__ float g_hB [MAXN*128];
__device__ float g_agg[MAXN*128];
__device__ float g_tmp[MAXN*128];
__device__ float g_cup[MAXN*3];
__device__ float g_eps[MAXN*3];
__device__ float g_deg[MAXN];
__device__ uint32_t g_wtf[550272];   // all weights pre-converted to tf32

// ---------------- helpers ----------------
__device__ __forceinline__ float tanh_ap(float x) {
    float t; asm("tanh.approx.f32 %0,%1;" : "=f"(t) : "f"(x)); return t;
}
__device__ __forceinline__ float silu(float x) {
    return 0.5f * x * (1.0f + tanh_ap(0.5f * x));
}
__device__ __forceinline__ uint32_t f2tf(float f) {
    uint32_t r; asm("cvt.rna.tf32.f32 %0, %1;" : "=r"(r) : "f"(f)); return r;
}
__device__ __forceinline__ uint32_t smem_u32(const void* p) {
    uint32_t a;
    asm("{ .reg .u64 t; cvta.to.shared.u64 t, %1; cvt.u32.u64 %0, t; }" : "=r"(a) : "l"(p));
    return a;
}
__device__ __forceinline__ void mma8(float d[4], uint32_t a0, uint32_t a1, uint32_t a2, uint32_t a3,
                                     uint32_t b0, uint32_t b1) {
    asm volatile(
        "mma.sync.aligned.m16n8k8.row.col.f32.tf32.tf32.f32 "
        "{%0,%1,%2,%3},{%4,%5,%6,%7},{%8,%9},{%0,%1,%2,%3};"
        : "+f"(d[0]), "+f"(d[1]), "+f"(d[2]), "+f"(d[3])
        : "r"(a0), "r"(a1), "r"(a2), "r"(a3), "r"(b0), "r"(b1));
}
__device__ __forceinline__ void red2(float* p, float a, float b) {
    asm volatile("red.global.add.v2.f32 [%0],{%1,%2};" :: "l"(p), "f"(a), "f"(b) : "memory");
}
__device__ __forceinline__ void red1(float* p, float a) {
    asm volatile("red.global.add.f32 [%0],%1;" :: "l"(p), "f"(a) : "memory");
}
__device__ __forceinline__ void cpa16(uint32_t saddr, const void* g) {
    asm volatile("cp.async.ca.shared.global [%0], [%1], 16;" :: "r"(saddr), "l"(g));
}
#define CP_COMMIT() asm volatile("cp.async.commit_group;" ::: "memory")
#define CP_WAIT1()  asm volatile("cp.async.wait_group 1;" ::: "memory")
#define CP_WAIT0()  asm volatile("cp.async.wait_group 0;" ::: "memory")

#define STRIDE 136
#define SA_BYTES (128*STRIDE*4)          // 69632
#define CHUNK_BYTES (32*STRIDE*4)        // 17408
#define SB0_OFF SA_BYTES
#define SB1_OFF (SA_BYTES + CHUNK_BYTES)
#define SMEM_AB (SA_BYTES + 2*CHUNK_BYTES)   // 104448

// stage one 32-row weight chunk (tf32 u32, row-major [k][128]) into smem via cp.async
__device__ __forceinline__ void prefetch_chunk(uint32_t dstAddr, const uint32_t* __restrict__ src, int tid) {
#pragma unroll
    for (int i = 0; i < 4; i++) {
        int u = tid + i * 256;           // 16B unit id, 1024 total
        int k = u >> 5, c4 = u & 31;
        cpa16(dstAddr + (uint32_t)(k * STRIDE + c4 * 4) * 4, src + k * 128 + c4 * 4);
    }
    CP_COMMIT();
}

__device__ __forceinline__ void mma_chunk(const uint32_t* __restrict__ sA,
                                          const uint32_t* __restrict__ sB,
                                          int warpM, int warpN, int lane, int kbase,
                                          float acc[2][8][4]) {
    int l4 = lane >> 2, lq = lane & 3;
    int rb = warpM * 32 + l4, nb = warpN * 64 + l4;
#pragma unroll
    for (int kk = 0; kk < 32; kk += 8) {
        int k0 = kbase + kk;
        uint32_t a[2][4];
#pragma unroll
        for (int mi = 0; mi < 2; mi++) {
            int r = rb + mi * 16;
            a[mi][0] = sA[r * STRIDE + k0 + lq];
            a[mi][1] = sA[(r + 8) * STRIDE + k0 + lq];
            a[mi][2] = sA[r * STRIDE + k0 + lq + 4];
            a[mi][3] = sA[(r + 8) * STRIDE + k0 + lq + 4];
        }
#pragma unroll
        for (int ni = 0; ni < 8; ni++) {
            int nn = nb + ni * 8;
            uint32_t b0 = sB[(kk + lq) * STRIDE + nn];
            uint32_t b1 = sB[(kk + lq + 4) * STRIDE + nn];
            mma8(acc[0][ni], a[0][0], a[0][1], a[0][2], a[0][3], b0, b1);
            mma8(acc[1][ni], a[1][0], a[1][1], a[1][2], a[1][3], b0, b1);
        }
    }
}
__device__ __forceinline__ void acc_zero(float acc[2][8][4]) {
#pragma unroll
    for (int mi = 0; mi < 2; mi++)
#pragma unroll
        for (int ni = 0; ni < 8; ni++)
#pragma unroll
            for (int j = 0; j < 4; j++) acc[mi][ni][j] = 0.0f;
}

// pipelined GEMM over nchunks 32-row weight chunks with double-buffered cp.async
__device__ __forceinline__ void pipe_gemm(const uint32_t* __restrict__ sA,
    const uint32_t* __restrict__ sB0, const uint32_t* __restrict__ sB1,
    uint32_t sb0a, uint32_t sb1a,
    const uint32_t* __restrict__ W, int nchunks, int tid,
    int warpM, int warpN, int lane, bool c0done, float acc[2][8][4])
{
    if (!c0done) prefetch_chunk(sb0a, W, tid);
    for (int c = 0; c < nchunks; c++) {
        if (c + 1 < nchunks) {
            prefetch_chunk((c & 1) ? sb0a : sb1a, W + (c + 1) * 4096, tid);
            CP_WAIT1();
        } else {
            CP_WAIT0();
        }
        __syncthreads();
        mma_chunk(sA, (c & 1) ? sB1 : sB0, warpM, warpN, lane, c * 32, acc);
        __syncthreads();
    }
}

// ---------------- weight pre-conversion ----------------
struct CvtArgs { const float* src[10]; int len[10]; int off[10]; };
__global__ void cvt_kernel(CvtArgs a) {
    int m = blockIdx.y;
    int i = blockIdx.x * blockDim.x + threadIdx.x;
    if (i < a.len[m]) g_wtf[a.off[m] + i] = f2tf(a.src[m][i]);
}

// ---------------- small utility kernels ----------------
__global__ void zero_kernel(float* p, int n) {
    int i = blockIdx.x * blockDim.x + threadIdx.x;
    if (i < n) p[i] = 0.0f;
}
__global__ void copy_kernel(const float* __restrict__ s, float* d, int n) {
    int i = blockIdx.x * blockDim.x + threadIdx.x;
    if (i < n) d[i] = s[i];
}
__global__ void indeg_kernel(const int* __restrict__ col, int E, float* deg) {
    int i = blockIdx.x * blockDim.x + threadIdx.x;
    if (i < E) atomicAdd(&deg[col[i]], 1.0f);
}

// ---------------- generic node GEMM: out = act(A@W + bias) ----------------
__global__ __launch_bounds__(256, 2) void gemm_mma(
    const float* __restrict__ A, int K,
    const uint32_t* __restrict__ Wtf,
    const float* __restrict__ bias,
    float* __restrict__ out, int n, int act)
{
    extern __shared__ char smem[];
    uint32_t* sA  = (uint32_t*)smem;
    uint32_t* sB0 = (uint32_t*)(smem + SB0_OFF);
    uint32_t* sB1 = (uint32_t*)(smem + SB1_OFF);
    uint32_t sbase = smem_u32(smem);
    int tid = threadIdx.x, wid = tid >> 5, lane = tid & 31;
    int warpM = wid & 3, warpN = wid >> 2;
    int m0 = blockIdx.x * 128;

    if (K == 128) {
        for (int idx = tid; idx < 16384; idx += 256) {
            int m = idx >> 7, k = idx & 127;
            int gm = m0 + m; if (gm >= n) gm = n - 1;
            sA[m * STRIDE + k] = f2tf(A[(size_t)gm * 128 + k]);
        }
    } else {  // K == 64
        for (int idx = tid; idx < 8192; idx += 256) {
            int m = idx >> 6, k = idx & 63;
            int gm = m0 + m; if (gm >= n) gm = n - 1;
            sA[m * STRIDE + k] = f2tf(A[(size_t)gm * 64 + k]);
        }
    }
    float acc[2][8][4];
    acc_zero(acc);
    pipe_gemm(sA, sB0, sB1, sbase + SB0_OFF, sbase + SB1_OFF,
              Wtf, K >> 5, tid, warpM, warpN, lane, false, acc);

    int l4 = lane >> 2, q2 = (lane & 3) * 2;
#pragma unroll
    for (int mi = 0; mi < 2; mi++)
#pragma unroll
        for (int half = 0; half < 2; half++) {
            int gm = m0 + warpM * 32 + mi * 16 + l4 + half * 8;
            if (gm >= n) continue;
            float* orow = out + (size_t)gm * 128;
#pragma unroll
            for (int ni = 0; ni < 8; ni++) {
                int c = warpN * 64 + ni * 8 + q2;
                float v0 = acc[mi][ni][half * 2 + 0];
                float v1 = acc[mi][ni][half * 2 + 1];
                if (bias) { float2 bv = *(const float2*)(bias + c); v0 += bv.x; v1 += bv.y; }
                if (act)  { v0 = silu(v0); v1 = silu(v1); }
                *(float2*)(orow + c) = make_float2(v0, v1);
            }
        }
}

// ---------------- dual projection: hA = h@Wa, hB = h@Wb (one A load) ----------------
__global__ __launch_bounds__(256, 2) void proj2(
    const float* __restrict__ A,
    const uint32_t* __restrict__ Wa, const uint32_t* __restrict__ Wb,
    float* __restrict__ outA, float* __restrict__ outB, int n)
{
    extern __shared__ char smem[];
    uint32_t* sA  = (uint32_t*)smem;
    uint32_t* sB0 = (uint32_t*)(smem + SB0_OFF);
    uint32_t* sB1 = (uint32_t*)(smem + SB1_OFF);
    uint32_t sbase = smem_u32(smem);
    int tid = threadIdx.x, wid = tid >> 5, lane = tid & 31;
    int warpM = wid & 3, warpN = wid >> 2;
    int m0 = blockIdx.x * 128;

    for (int idx = tid; idx < 16384; idx += 256) {
        int m = idx >> 7, k = idx & 127;
        int gm = m0 + m; if (gm >= n) gm = n - 1;
        sA[m * STRIDE + k] = f2tf(A[(size_t)gm * 128 + k]);
    }
    float acc[2][8][4];
    int l4 = lane >> 2, q2 = (lane & 3) * 2;

    acc_zero(acc);
    pipe_gemm(sA, sB0, sB1, sbase + SB0_OFF, sbase + SB1_OFF,
              Wa, 4, tid, warpM, warpN, lane, false, acc);
    prefetch_chunk(sbase + SB0_OFF, Wb, tid);   // overlap with epilogue A
#pragma unroll
    for (int mi = 0; mi < 2; mi++)
#pragma unroll
        for (int half = 0; half < 2; half++) {
            int gm = m0 + warpM * 32 + mi * 16 + l4 + half * 8;
            if (gm >= n) continue;
            float* orow = outA + (size_t)gm * 128;
#pragma unroll
            for (int ni = 0; ni < 8; ni++) {
                int c = warpN * 64 + ni * 8 + q2;
                *(float2*)(orow + c) = make_float2(acc[mi][ni][half*2+0], acc[mi][ni][half*2+1]);
            }
        }
    acc_zero(acc);
    pipe_gemm(sA, sB0, sB1, sbase + SB0_OFF, sbase + SB1_OFF,
              Wb, 4, tid, warpM, warpN, lane, true, acc);
#pragma unroll
    for (int mi = 0; mi < 2; mi++)
#pragma unroll
        for (int half = 0; half < 2; half++) {
            int gm = m0 + warpM * 32 + mi * 16 + l4 + half * 8;
            if (gm >= n) continue;
            float* orow = outB + (size_t)gm * 128;
#pragma unroll
            for (int ni = 0; ni < 8; ni++) {
                int c = warpN * 64 + ni * 8 + q2;
                *(float2*)(orow + c) = make_float2(acc[mi][ni][half*2+0], acc[mi][ni][half*2+1]);
            }
        }
}

// ---------------- fused: tmp = silu(h@Wa + agg@Wb + b1) ----------------
__global__ __launch_bounds__(256, 2) void fused_tmp(
    const float* __restrict__ A1, const float* __restrict__ A2,
    const uint32_t* __restrict__ Wa, const uint32_t* __restrict__ Wb,
    const float* __restrict__ bias,
    float* __restrict__ out, int n)
{
    extern __shared__ char smem[];
    uint32_t* sA  = (uint32_t*)smem;
    uint32_t* sB0 = (uint32_t*)(smem + SB0_OFF);
    uint32_t* sB1 = (uint32_t*)(smem + SB1_OFF);
    uint32_t sbase = smem_u32(smem);
    int tid = threadIdx.x, wid = tid >> 5, lane = tid & 31;
    int warpM = wid & 3, warpN = wid >> 2;
    int m0 = blockIdx.x * 128;

    for (int idx = tid; idx < 16384; idx += 256) {
        int m = idx >> 7, k = idx & 127;
        int gm = m0 + m; if (gm >= n) gm = n - 1;
        sA[m * STRIDE + k] = f2tf(A1[(size_t)gm * 128 + k]);
    }
    float acc[2][8][4];
    acc_zero(acc);
    pipe_gemm(sA, sB0, sB1, sbase + SB0_OFF, sbase + SB1_OFF,
              Wa, 4, tid, warpM, warpN, lane, false, acc);
    prefetch_chunk(sbase + SB0_OFF, Wb, tid);
    // reload A tile from A2 (agg); safe: all mma consumed sA (sync inside pipe)
    for (int idx = tid; idx < 16384; idx += 256) {
        int m = idx >> 7, k = idx & 127;
        int gm = m0 + m; if (gm >= n) gm = n - 1;
        sA[m * STRIDE + k] = f2tf(A2[(size_t)gm * 128 + k]);
    }
    pipe_gemm(sA, sB0, sB1, sbase + SB0_OFF, sbase + SB1_OFF,
              Wb, 4, tid, warpM, warpN, lane, true, acc);   // accumulate

    int l4 = lane >> 2, q2 = (lane & 3) * 2;
#pragma unroll
    for (int mi = 0; mi < 2; mi++)
#pragma unroll
        for (int half = 0; half < 2; half++) {
            int gm = m0 + warpM * 32 + mi * 16 + l4 + half * 8;
            if (gm >= n) continue;
            float* orow = out + (size_t)gm * 128;
#pragma unroll
            for (int ni = 0; ni < 8; ni++) {
                int c = warpN * 64 + ni * 8 + q2;
                float2 bv = *(const float2*)(bias + c);
                *(float2*)(orow + c) = make_float2(silu(acc[mi][ni][half*2+0] + bv.x),
                                                   silu(acc[mi][ni][half*2+1] + bv.y));
            }
        }
}

// ---------------- fused: h = LN(h + tmp@W2 + b2); x += cup/(deg+1) ----------------
__global__ __launch_bounds__(256, 2) void gemm_ln(
    const float* __restrict__ A,
    const uint32_t* __restrict__ Wtf,
    const float* __restrict__ bias,
    const float* __restrict__ lng, const float* __restrict__ lnb,
    float* __restrict__ h, float* __restrict__ x,
    const float* __restrict__ cup, const float* __restrict__ deg, int n)
{
    extern __shared__ char smem[];
    uint32_t* sA  = (uint32_t*)smem;
    uint32_t* sB0 = (uint32_t*)(smem + SB0_OFF);
    uint32_t* sB1 = (uint32_t*)(smem + SB1_OFF);
    float* sSum = (float*)(smem + SMEM_AB);
    float* sSq  = (float*)(smem + SMEM_AB + 512);
    uint32_t sbase = smem_u32(smem);
    int tid = threadIdx.x, wid = tid >> 5, lane = tid & 31;
    int warpM = wid & 3, warpN = wid >> 2;
    int m0 = blockIdx.x * 128;

    if (tid < 128) { sSum[tid] = 0.0f; sSq[tid] = 0.0f; }
    for (int idx = tid; idx < 16384; idx += 256) {
        int m = idx >> 7, k = idx & 127;
        int gm = m0 + m; if (gm >= n) gm = n - 1;
        sA[m * STRIDE + k] = f2tf(A[(size_t)gm * 128 + k]);
    }
    float acc[2][8][4];
    acc_zero(acc);
    pipe_gemm(sA, sB0, sB1, sbase + SB0_OFF, sbase + SB1_OFF,
              Wtf, 4, tid, warpM, warpN, lane, false, acc);

    int l4 = lane >> 2, q2 = (lane & 3) * 2;
    // phase 1: val = h + acc + bias -> overwrite h (pre-LN); accumulate row sums
#pragma unroll
    for (int mi = 0; mi < 2; mi++)
#pragma unroll
        for (int half = 0; half < 2; half++) {
            int rl = warpM * 32 + mi * 16 + l4 + half * 8;
            int gm = m0 + rl;
            float s = 0.0f, s2 = 0.0f;
            if (gm < n) {
                float* hrow = h + (size_t)gm * 128;
#pragma unroll
                for (int ni = 0; ni < 8; ni++) {
                    int c = warpN * 64 + ni * 8 + q2;
                    float2 bv = *(const float2*)(bias + c);
                    float2 hv = *(const float2*)(hrow + c);
                    float v0 = acc[mi][ni][half*2+0] + bv.x + hv.x;
                    float v1 = acc[mi][ni][half*2+1] + bv.y + hv.y;
                    *(float2*)(hrow + c) = make_float2(v0, v1);
                    s += v0 + v1; s2 += v0*v0 + v1*v1;
                }
            }
            s  += __shfl_xor_sync(0xffffffffu, s, 1);
            s  += __shfl_xor_sync(0xffffffffu, s, 2);
            s2 += __shfl_xor_sync(0xffffffffu, s2, 1);
            s2 += __shfl_xor_sync(0xffffffffu, s2, 2);
            if ((lane & 3) == 0 && gm < n) {
                atomicAdd(&sSum[rl], s);
                atomicAdd(&sSq[rl], s2);
            }
        }
    __syncthreads();
    // phase 2: normalize
    for (int idx = tid; idx < 16384; idx += 256) {
        int rl = idx >> 7, c = idx & 127;
        int gm = m0 + rl;
        if (gm >= n) continue;
        float mu = sSum[rl] * (1.0f / 128.0f);
        float var = sSq[rl] * (1.0f / 128.0f) - mu * mu;
        float val = h[(size_t)gm * 128 + c];
        h[(size_t)gm * 128 + c] = (val - mu) * rsqrtf(var + 1e-5f) * lng[c] + lnb[c];
    }
    if (tid < 128) {
        int gm = m0 + tid;
        if (gm < n) {
            float inv = __fdividef(1.0f, deg[gm] + 1.0f);
            x[gm*3 + 0] += cup[gm*3 + 0] * inv;
            x[gm*3 + 1] += cup[gm*3 + 1] * inv;
            x[gm*3 + 2] += cup[gm*3 + 2] * inv;
        }
    }
}

// ---------------- fused edge kernel (message-passing layer) ----------------
__global__ __launch_bounds__(256, 2) void edge_layer_mma(
    const int* __restrict__ eRow, const int* __restrict__ eCol, int E,
    const float* __restrict__ x,
    const float* __restrict__ hA, const float* __restrict__ hB,
    const float* __restrict__ w1c, const float* __restrict__ b1,
    const uint32_t* __restrict__ W2tf, const float* __restrict__ b2,
    const uint32_t* __restrict__ Cw1tf, const float* __restrict__ cb1,
    const float* __restrict__ cw2,
    float* __restrict__ agg, float* __restrict__ cupd)
{
    extern __shared__ char smem[];
    uint32_t* sA  = (uint32_t*)smem;
    uint32_t* sB0 = (uint32_t*)(smem + SB0_OFF);
    uint32_t* sB1 = (uint32_t*)(smem + SB1_OFF);
    char* aux = smem + SMEM_AB;
    int*   sRow   = (int*)(aux);
    int*   sCol   = (int*)(aux + 512);
    int*   sValid = (int*)(aux + 1024);
    float* sDist  = (float*)(aux + 1536);
    float* sRelx  = (float*)(aux + 2048);
    float* sRely  = (float*)(aux + 2560);
    float* sRelz  = (float*)(aux + 3072);
    float* sPart  = (float*)(aux + 3584);
    uint32_t sbase = smem_u32(smem);

    int tid = threadIdx.x, wid = tid >> 5, lane = tid & 31;
    int warpM = wid & 3, warpN = wid >> 2;
    int e0 = blockIdx.x * 128;

    prefetch_chunk(sbase + SB0_OFF, W2tf, tid);   // start weight fetch immediately

    if (tid < 128) {
        sPart[tid] = 0.0f;
        int e = e0 + tid;
        int valid = (e < E); if (!valid) e = E - 1;
        int r = eRow[e], c = eCol[e];
        float rx = x[r*3]   - x[c*3];
        float ry = x[r*3+1] - x[c*3+1];
        float rz = x[r*3+2] - x[c*3+2];
        float d = sqrtf(rx*rx + ry*ry + rz*rz);
        sRow[tid] = r; sCol[tid] = c; sValid[tid] = valid;
        sDist[tid] = d; sRelx[tid] = rx; sRely[tid] = ry; sRelz[tid] = rz;
    }
    __syncthreads();

    {   // sA[e][k] = silu(t1), two threads per edge
        int e = tid >> 1, j0 = (tid & 1) * 64;
        int r = sRow[e], c = sCol[e];
        float d = sDist[e];
        const float4* pa  = (const float4*)(hA  + (size_t)r * 128 + j0);
        const float4* pb  = (const float4*)(hB  + (size_t)c * 128 + j0);
        const float4* pw  = (const float4*)(w1c + j0);
        const float4* pb1 = (const float4*)(b1  + j0);
        uint32_t* dst = sA + e * STRIDE + j0;
#pragma unroll
        for (int q = 0; q < 16; q++) {
            float4 a = pa[q], b = pb[q], w = pw[q], bb = pb1[q];
            uint4 v;
            v.x = f2tf(silu(a.x + b.x + d * w.x + bb.x));
            v.y = f2tf(silu(a.y + b.y + d * w.y + bb.y));
            v.z = f2tf(silu(a.z + b.z + d * w.z + bb.z));
            v.w = f2tf(silu(a.w + b.w + d * w.w + bb.w));
            *(uint4*)(dst + q * 4) = v;
        }
    }

    float acc[2][8][4];
    acc_zero(acc);
    pipe_gemm(sA, sB0, sB1, sbase + SB0_OFF, sbase + SB1_OFF,
              W2tf, 4, tid, warpM, warpN, lane, true, acc);   // D1 = U @ m_w2

    prefetch_chunk(sbase + SB0_OFF, Cw1tf, tid);   // overlap with epilogue

    int l4 = lane >> 2, q2 = (lane & 3) * 2;
    {   // msg = silu(D1 + b2): tf32 into sA for GEMM2, fp32 scatter into agg
        float2 bv[8];
#pragma unroll
        for (int ni = 0; ni < 8; ni++) bv[ni] = *(const float2*)(b2 + warpN * 64 + ni * 8 + q2);
#pragma unroll
        for (int mi = 0; mi < 2; mi++)
#pragma unroll
            for (int half = 0; half < 2; half++) {
                int e = warpM * 32 + mi * 16 + l4 + half * 8;
                int valid = sValid[e];
                int cn = sCol[e];
#pragma unroll
                for (int ni = 0; ni < 8; ni++) {
                    int c = warpN * 64 + ni * 8 + q2;
                    float m0 = silu(acc[mi][ni][half*2+0] + bv[ni].x);
                    float m1 = silu(acc[mi][ni][half*2+1] + bv[ni].y);
                    uint2 t; t.x = f2tf(m0); t.y = f2tf(m1);
                    *(uint2*)(sA + e * STRIDE + c) = t;
                    if (valid) red2(agg + (size_t)cn * 128 + c, m0, m1);
                }
            }
    }
    acc_zero(acc);
    pipe_gemm(sA, sB0, sB1, sbase + SB0_OFF, sbase + SB1_OFF,
              Cw1tf, 4, tid, warpM, warpN, lane, true, acc);   // D2 = msg @ c_w1

    // per-edge dot: sum_c silu(D2 + cb1[c]) * cw2[c]
    float2 cbv[8], cwv[8];
#pragma unroll
    for (int ni = 0; ni < 8; ni++) {
        int c = warpN * 64 + ni * 8 + q2;
        cbv[ni] = *(const float2*)(cb1 + c);
        cwv[ni] = *(const float2*)(cw2 + c);
    }
    float p[2][2];
    p[0][0] = p[0][1] = p[1][0] = p[1][1] = 0.0f;
#pragma unroll
    for (int ni = 0; ni < 8; ni++)
#pragma unroll
        for (int mi = 0; mi < 2; mi++)
#pragma unroll
            for (int half = 0; half < 2; half++)
                p[mi][half] += silu(acc[mi][ni][half*2+0] + cbv[ni].x) * cwv[ni].x
                             + silu(acc[mi][ni][half*2+1] + cbv[ni].y) * cwv[ni].y;
#pragma unroll
    for (int mi = 0; mi < 2; mi++)
#pragma unroll
        for (int half = 0; half < 2; half++) {
            p[mi][half] += __shfl_xor_sync(0xffffffffu, p[mi][half], 1);
            p[mi][half] += __shfl_xor_sync(0xffffffffu, p[mi][half], 2);
        }
    if ((lane & 3) == 0) {
#pragma unroll
        for (int mi = 0; mi < 2; mi++)
#pragma unroll
            for (int half = 0; half < 2; half++)
                atomicAdd(&sPart[warpM * 32 + mi * 16 + l4 + half * 8], p[mi][half]);
    }
    __syncthreads();

    if (tid < 128 && sValid[tid]) {
        float cm = tanh_ap(sPart[tid]);
        float f = __fdividef(cm, sDist[tid] + 1e-8f);
        int c = sCol[tid];
        red1(cupd + c*3 + 0, f * sRelx[tid]);
        red1(cupd + c*3 + 1, f * sRely[tid]);
        red1(cupd + c*3 + 2, f * sRelz[tid]);
    }
}

// ---------------- fused edge kernel (epsilon head) ----------------
__global__ __launch_bounds__(256, 2) void edge_eps_mma(
    const int* __restrict__ eRow, const int* __restrict__ eCol, int E,
    const float* __restrict__ x,
    const float* __restrict__ hA, const float* __restrict__ hB,
    const float* __restrict__ wRel, const float* __restrict__ b1,
    const uint32_t* __restrict__ W2tf, const float* __restrict__ b2,
    const uint32_t* __restrict__ Cw1tf, const float* __restrict__ cb1,
    const float* __restrict__ cw2, const float* __restrict__ cb2,
    float* __restrict__ eps)
{
    extern __shared__ char smem[];
    uint32_t* sA  = (uint32_t*)smem;
    uint32_t* sB0 = (uint32_t*)(smem + SB0_OFF);
    uint32_t* sB1 = (uint32_t*)(smem + SB1_OFF);
    char* aux = smem + SMEM_AB;
    int*   sRow   = (int*)(aux);
    int*   sCol   = (int*)(aux + 512);
    int*   sValid = (int*)(aux + 1024);
    float* sDist  = (float*)(aux + 1536);
    float* sRelx  = (float*)(aux + 2048);
    float* sRely  = (float*)(aux + 2560);
    float* sRelz  = (float*)(aux + 3072);
    float* sPart  = (float*)(aux + 3584);   // 384 floats
    uint32_t sbase = smem_u32(smem);

    int tid = threadIdx.x, wid = tid >> 5, lane = tid & 31;
    int warpM = wid & 3, warpN = wid >> 2;
    int e0 = blockIdx.x * 128;

    prefetch_chunk(sbase + SB0_OFF, W2tf, tid);

    for (int i = tid; i < 384; i += 256) sPart[i] = 0.0f;
    if (tid < 128) {
        int e = e0 + tid;
        int valid = (e < E); if (!valid) e = E - 1;
        int r = eRow[e], c = eCol[e];
        float rx = x[r*3]   - x[c*3];
        float ry = x[r*3+1] - x[c*3+1];
        float rz = x[r*3+2] - x[c*3+2];
        float d = sqrtf(rx*rx + ry*ry + rz*rz);
        sRow[tid] = r; sCol[tid] = c; sValid[tid] = valid;
        sDist[tid] = d; sRelx[tid] = rx; sRely[tid] = ry; sRelz[tid] = rz;
    }
    __syncthreads();

    {
        int e = tid >> 1, j0 = (tid & 1) * 64;
        int r = sRow[e], c = sCol[e];
        float d = sDist[e], rx = sRelx[e], ry = sRely[e], rz = sRelz[e];
        const float4* pa  = (const float4*)(hA + (size_t)r * 128 + j0);
        const float4* pb  = (const float4*)(hB + (size_t)c * 128 + j0);
        const float4* pwx = (const float4*)(wRel + j0);
        const float4* pwy = (const float4*)(wRel + 128 + j0);
        const float4* pwz = (const float4*)(wRel + 256 + j0);
        const float4* pwd = (const float4*)(wRel + 384 + j0);
        const float4* pb1 = (const float4*)(b1 + j0);
        uint32_t* dst = sA + e * STRIDE + j0;
#pragma unroll
        for (int q = 0; q < 16; q++) {
            float4 a = pa[q], b = pb[q];
            float4 wx = pwx[q], wy = pwy[q], wz = pwz[q], wd = pwd[q], bb = pb1[q];
            uint4 v;
            v.x = f2tf(silu(a.x + b.x + rx*wx.x + ry*wy.x + rz*wz.x + d*wd.x + bb.x));
            v.y = f2tf(silu(a.y + b.y + rx*wx.y + ry*wy.y + rz*wz.y + d*wd.y + bb.y));
            v.z = f2tf(silu(a.z + b.z + rx*wx.z + ry*wy.z + rz*wz.z + d*wd.z + bb.z));
            v.w = f2tf(silu(a.w + b.w + rx*wx.w + ry*wy.w + rz*wz.w + d*wd.w + bb.w));
            *(uint4*)(dst + q * 4) = v;
        }
    }

    float acc[2][8][4];
    acc_zero(acc);
    pipe_gemm(sA, sB0, sB1, sbase + SB0_OFF, sbase + SB1_OFF,
              W2tf, 4, tid, warpM, warpN, lane, true, acc);

    prefetch_chunk(sbase + SB0_OFF, Cw1tf, tid);

    int l4 = lane >> 2, q2 = (lane & 3) * 2;
    {
        float2 bv[8];
#pragma unroll
        for (int ni = 0; ni < 8; ni++) bv[ni] = *(const float2*)(b2 + warpN * 64 + ni * 8 + q2);
#pragma unroll
        for (int mi = 0; mi < 2; mi++)
#pragma unroll
            for (int half = 0; half < 2; half++) {
                int e = warpM * 32 + mi * 16 + l4 + half * 8;
#pragma unroll
                for (int ni = 0; ni < 8; ni++) {
                    int c = warpN * 64 + ni * 8 + q2;
                    uint2 t;
                    t.x = f2tf(silu(acc[mi][ni][half*2+0] + bv[ni].x));
                    t.y = f2tf(silu(acc[mi][ni][half*2+1] + bv[ni].y));
                    *(uint2*)(sA + e * STRIDE + c) = t;
                }
            }
    }
    acc_zero(acc);
    pipe_gemm(sA, sB0, sB1, sbase + SB0_OFF, sbase + SB1_OFF,
              Cw1tf, 4, tid, warpM, warpN, lane, true, acc);

    float p[2][2][3];
#pragma unroll
    for (int mi = 0; mi < 2; mi++)
#pragma unroll
        for (int half = 0; half < 2; half++)
            p[mi][half][0] = p[mi][half][1] = p[mi][half][2] = 0.0f;
#pragma unroll
    for (int ni = 0; ni < 8; ni++) {
        int c = warpN * 64 + ni * 8 + q2;
        float2 cbv = *(const float2*)(cb1 + c);
        float w00 = cw2[c*3+0], w01 = cw2[c*3+1], w02 = cw2[c*3+2];
        float w10 = cw2[c*3+3], w11 = cw2[c*3+4], w12 = cw2[c*3+5];
#pragma unroll
        for (int mi = 0; mi < 2; mi++)
#pragma unroll
            for (int half = 0; half < 2; half++) {
                float v0 = silu(acc[mi][ni][half*2+0] + cbv.x);
                float v1 = silu(acc[mi][ni][half*2+1] + cbv.y);
                p[mi][half][0] += v0*w00 + v1*w10;
                p[mi][half][1] += v0*w01 + v1*w11;
                p[mi][half][2] += v0*w02 + v1*w12;
            }
    }
#pragma unroll
    for (int mi = 0; mi < 2; mi++)
#pragma unroll
        for (int half = 0; half < 2; half++)
#pragma unroll
            for (int d = 0; d < 3; d++) {
                p[mi][half][d] += __shfl_xor_sync(0xffffffffu, p[mi][half][d], 1);
                p[mi][half][d] += __shfl_xor_sync(0xffffffffu, p[mi][half][d], 2);
            }
    if ((lane & 3) == 0) {
#pragma unroll
        for (int mi = 0; mi < 2; mi++)
#pragma unroll
            for (int half = 0; half < 2; half++) {
                int e = warpM * 32 + mi * 16 + l4 + half * 8;
                atomicAdd(&sPart[e*3 + 0], p[mi][half][0]);
                atomicAdd(&sPart[e*3 + 1], p[mi][half][1]);
                atomicAdd(&sPart[e*3 + 2], p[mi][half][2]);
            }
    }
    __syncthreads();

    if (tid < 128 && sValid[tid]) {
        int c = sCol[tid];
        red1(eps + c*3 + 0, sPart[tid*3 + 0] + cb2[0]);
        red1(eps + c*3 + 1, sPart[tid*3 + 1] + cb2[1]);
        red1(eps + c*3 + 2, sPart[tid*3 + 2] + cb2[2]);
    }
}

// ---------------- eps node head ----------------
__global__ void eps_final2(const float* __restrict__ t, const float* __restrict__ x,
                           const float* __restrict__ w1x3, const float* __restrict__ b1,
                           const float* __restrict__ W2, const float* __restrict__ b2,
                           float* __restrict__ eps)
{
    int node = blockIdx.x;
    int tid = threadIdx.x;   // 96 threads
    int d = tid >> 5, lane = tid & 31;
    float x0 = x[node*3], x1 = x[node*3+1], x2 = x[node*3+2];
    float p = 0.0f;
    for (int k = lane; k < 128; k += 32) {
        float v = t[(size_t)node*128 + k] + x0*w1x3[k] + x1*w1x3[128+k] + x2*w1x3[256+k] + b1[k];
        p += silu(v) * W2[k*3 + d];
    }
#pragma unroll
    for (int m = 16; m >= 1; m >>= 1) p += __shfl_xor_sync(0xffffffffu, p, m);
    if (lane == 0) eps[node*3 + d] += p + b2[d];
}

// ---------------- pack output: [h | x | eps] ----------------
__global__ void pack_kernel(const float* __restrict__ h, const float* __restrict__ x,
                            const float* __restrict__ eps, float* __restrict__ out, int n)
{
    int i = blockIdx.x * blockDim.x + threadIdx.x;
    int nh = n * 128;
    if (i < nh) out[i] = h[i];
    else if (i < nh + 3*n) out[i] = x[i - nh];
    else if (i < nh + 6*n) out[i] = eps[i - nh - 3*n];
}

// ---------------- host ----------------
static const int NODE_SMEM = SMEM_AB;            // 104448
static const int LN_SMEM   = SMEM_AB + 1024;     // 105472
static const int EDGE_SMEM = SMEM_AB + 5120;     // 109568

// g_wtf offsets
#define OFF_MW1  0
#define OFF_MW2  131584
#define OFF_CW1  197120
#define OFF_NW1  262656
#define OFF_NW2  393728
#define OFF_EMW1 459264
#define OFF_EMW2 492544
#define OFF_ECW1 508928
#define OFF_EHW1 525312
#define OFF_EMB  542080

extern "C" void kernel_launch(void* const* d_in, const int* in_sizes, int n_in,
                              void* d_out, int out_size)
{
    const float* in_h  = (const float*)d_in[0];
    const float* in_x  = (const float*)d_in[1];
    const int*   eidx  = (const int*)d_in[2];
    const float* emb_w = (const float*)d_in[3];
    const float* emb_b = (const float*)d_in[4];
    const float* m_w1  = (const float*)d_in[5];
    const float* m_b1  = (const float*)d_in[6];
    const float* m_w2  = (const float*)d_in[7];
    const float* m_b2  = (const float*)d_in[8];
    const float* c_w1  = (const float*)d_in[9];
    const float* c_b1  = (const float*)d_in[10];
    const float* c_w2  = (const float*)d_in[11];
    const float* n_w1  = (const float*)d_in[12];
    const float* n_b1  = (const float*)d_in[13];
    const float* n_w2  = (const float*)d_in[14];
    const float* n_b2  = (const float*)d_in[15];
    const float* ln_g  = (const float*)d_in[16];
    const float* ln_b  = (const float*)d_in[17];
    const float* em_w1 = (const float*)d_in[18];
    const float* em_b1 = (const float*)d_in[19];
    const float* em_w2 = (const float*)d_in[20];
    const float* em_b2 = (const float*)d_in[21];
    const float* ec_w1 = (const float*)d_in[22];
    const float* ec_b1 = (const float*)d_in[23];
    const float* ec_w2 = (const float*)d_in[24];
    const float* ec_b2 = (const float*)d_in[25];
    const float* eh_w1 = (const float*)d_in[26];
    const float* eh_b1 = (const float*)d_in[27];
    const float* eh_w2 = (const float*)d_in[28];
    const float* eh_b2 = (const float*)d_in[29];

    int n = in_sizes[0] / 64;
    int E = in_sizes[2] / 2;
    const int* eRow = eidx;
    const int* eCol = eidx + E;

    float *h, *x, *hA, *hB, *agg, *tmp, *cup, *eps, *deg;
    uint32_t* wtf;
    cudaGetSymbolAddress((void**)&h,   g_h);
    cudaGetSymbolAddress((void**)&x,   g_x);
    cudaGetSymbolAddress((void**)&hA,  g_hA);
    cudaGetSymbolAddress((void**)&hB,  g_hB);
    cudaGetSymbolAddress((void**)&agg, g_agg);
    cudaGetSymbolAddress((void**)&tmp, g_tmp);
    cudaGetSymbolAddress((void**)&cup, g_cup);
    cudaGetSymbolAddress((void**)&eps, g_eps);
    cudaGetSymbolAddress((void**)&deg, g_deg);
    cudaGetSymbolAddress((void**)&wtf, g_wtf);

    cudaFuncSetAttribute(gemm_mma,       cudaFuncAttributeMaxDynamicSharedMemorySize, NODE_SMEM);
    cudaFuncSetAttribute(proj2,          cudaFuncAttributeMaxDynamicSharedMemorySize, NODE_SMEM);
    cudaFuncSetAttribute(fused_tmp,      cudaFuncAttributeMaxDynamicSharedMemorySize, NODE_SMEM);
    cudaFuncSetAttribute(gemm_ln,        cudaFuncAttributeMaxDynamicSharedMemorySize, LN_SMEM);
    cudaFuncSetAttribute(edge_layer_mma, cudaFuncAttributeMaxDynamicSharedMemorySize, EDGE_SMEM);
    cudaFuncSetAttribute(edge_eps_mma,   cudaFuncAttributeMaxDynamicSharedMemorySize, EDGE_SMEM);

    // pre-convert all weights to tf32
    {
        CvtArgs a;
        const float* srcs[10] = {m_w1, m_w2, c_w1, n_w1, n_w2, em_w1, em_w2, ec_w1, eh_w1, emb_w};
        int lens[10] = {131584, 65536, 65536, 131072, 65536, 33280, 16384, 16384, 16768, 8192};
        int offs[10] = {OFF_MW1, OFF_MW2, OFF_CW1, OFF_NW1, OFF_NW2, OFF_EMW1, OFF_EMW2, OFF_ECW1, OFF_EHW1, OFF_EMB};
        for (int i = 0; i < 10; i++) { a.src[i] = srcs[i]; a.len[i] = lens[i]; a.off[i] = offs[i]; }
        dim3 g((131584 + 255) / 256, 10);
        cvt_kernel<<<g, 256>>>(a);
    }

    int gN = (n + 127) / 128;
    int gE = (E + 127) / 128;

    zero_kernel<<<(n + 255)/256, 256>>>(deg, n);
    indeg_kernel<<<(E + 255)/256, 256>>>(eCol, E, deg);

    gemm_mma<<<gN, 256, NODE_SMEM>>>(in_h, 64, wtf + OFF_EMB, emb_b, h, n, 0);
    copy_kernel<<<(3*n + 255)/256, 256>>>(in_x, x, 3*n);

    for (int i = 0; i < 4; i++) {
        const uint32_t* w1a = wtf + OFF_MW1 + (size_t)i*257*128;
        proj2<<<gN, 256, NODE_SMEM>>>(h, w1a, w1a + 16384, hA, hB, n);
        zero_kernel<<<(n*128 + 255)/256, 256>>>(agg, n*128);
        zero_kernel<<<(3*n + 255)/256, 256>>>(cup, 3*n);
        edge_layer_mma<<<gE, 256, EDGE_SMEM>>>(
            eRow, eCol, E, x, hA, hB,
            m_w1 + (size_t)i*257*128 + 256*128, m_b1 + i*128,
            wtf + OFF_MW2 + i*16384, m_b2 + i*128,
            wtf + OFF_CW1 + i*16384, c_b1 + i*128, c_w2 + i*128,
            agg, cup);
        fused_tmp<<<gN, 256, NODE_SMEM>>>(h, agg,
            wtf + OFF_NW1 + i*32768, wtf + OFF_NW1 + i*32768 + 16384,
            n_b1 + i*128, tmp, n);
        gemm_ln<<<gN, 256, LN_SMEM>>>(tmp, wtf + OFF_NW2 + i*16384, n_b2 + i*128,
            ln_g + i*128, ln_b + i*128, h, x, cup, deg, n);
    }

    proj2<<<gN, 256, NODE_SMEM>>>(h, wtf + OFF_EMW1, wtf + OFF_EMW1 + 16384, hA, hB, n);
    zero_kernel<<<(3*n + 255)/256, 256>>>(eps, 3*n);
    edge_eps_mma<<<gE, 256, EDGE_SMEM>>>(
        eRow, eCol, E, x, hA, hB,
        em_w1 + 256*128, em_b1,
        wtf + OFF_EMW2, em_b2, wtf + OFF_ECW1, ec_b1, ec_w2, ec_b2, eps);
    gemm_mma<<<gN, 256, NODE_SMEM>>>(h, 128, wtf + OFF_EHW1, nullptr, tmp, n, 0);
    eps_final2<<<n, 96>>>(tmp, x, eh_w1 + 128*128, eh_b1, eh_w2, eh_b2, eps);

    pack_kernel<<<(n*134 + 255)/256, 256>>>(h, x, eps, (float*)d_out, n);
}